// round 9
// baseline (speedup 1.0000x reference)
#include <cuda_runtime.h>
#include <cuda_bf16.h>
#include <math.h>
#include <stdint.h>

#define BB    4
#define TPP   4
#define TFF   2
#define NPAIR (BB*TFF)
#define RAD   4
#define NS    81
#define NFR   (BB*TPP)

// ---------------- scratch ---------------------------------------------------------
__device__ int   g_idx[NPAIR];
__device__ int   g_needed[NFR];
__device__ float g_pf0[(size_t)NFR * 128 * 6400];
__device__ float g_pf1[(size_t)NFR * 256 * 1600];
__device__ float g_pf2[(size_t)NFR * 512 * 400];
__device__ __nv_bfloat16 g_w0a[128*128],  g_w0b[128*128];
__device__ __nv_bfloat16 g_w1a[256*256],  g_w1b[256*256];
__device__ __nv_bfloat16 g_w2a[512*512],  g_w2b[512*512];
__device__ __nv_bfloat16 g_x0a[(size_t)NFR*128*6400], g_x0b[(size_t)NFR*128*6400];
__device__ __nv_bfloat16 g_x1a[(size_t)NFR*256*1664], g_x1b[(size_t)NFR*256*1664];
__device__ __nv_bfloat16 g_x2a[(size_t)NFR*512*512],  g_x2b[(size_t)NFR*512*512];

// ---------------- prep ------------------------------------------------------------
__global__ void prep_kernel(const int* __restrict__ pci, const int* __restrict__ fci)
{
    if (threadIdx.x != 0 || blockIdx.x != 0) return;
    for (int n = 0; n < NFR; n++) g_needed[n] = 0;
    for (int i = 0; i < BB; i++) {
        int p_pos = TPP - 2;
        for (int j = 0; j < TFF; j++) {
            int f_i = fci[i * TFF + j];
            while (p_pos >= 0) {
                if (p_pos == 0 || f_i < -pci[i * TPP + p_pos - 1]) {
                    int id = p_pos + i * TPP;
                    g_idx[i * TFF + j] = id;
                    g_needed[id] = 1;
                    break;
                }
                p_pos--;
            }
        }
        g_needed[i * TPP + (TPP - 1)] = 1;
    }
}

// ---------------- fused split kernels ---------------------------------------------
union BV8 { __nv_bfloat16 h[8]; uint4 u; };

__device__ __forceinline__ void split8(const float* v, uint4* ua, uint4* ub)
{
    BV8 a, b;
#pragma unroll
    for (int j = 0; j < 8; j++) {
        __nv_bfloat16 h = __float2bfloat16(v[j]);
        a.h[j] = h;
        b.h[j] = __float2bfloat16(v[j] - __bfloat162float(h));
    }
    *ua = a.u; *ub = b.u;
}

struct SplitW {
    const float* w[3];
    __nv_bfloat16 *wa[3], *wb[3];
};

__global__ void wsplit_all(SplitW S)
{
    int lvl = blockIdx.y;
    int nE  = (128 << lvl) * (128 << lvl);
    int i   = (blockIdx.x * 256 + threadIdx.x) * 8;
    if (i < nE) {
        float v[8];
        *(float4*)&v[0] = *(const float4*)(S.w[lvl] + i);
        *(float4*)&v[4] = *(const float4*)(S.w[lvl] + i + 4);
        split8(v, (uint4*)(S.wa[lvl] + i), (uint4*)(S.wb[lvl] + i));
    }
}

struct SplitX {
    const float* x[3];
    __nv_bfloat16 *xa[3], *xb[3];
};

__global__ void xsplit_all(SplitX S)
{
    int n = blockIdx.z;
    if (!g_needed[n]) return;
    int lvl = blockIdx.y;
    const int C     = 128 << lvl;
    const int HW    = 6400 >> (2 * lvl);
    const int HWpad = (lvl == 0) ? 6400 : (lvl == 1 ? 1664 : 512);
    int tot = C * HWpad;
    int i = (blockIdx.x * 256 + threadIdx.x) * 8;
    if (i >= tot) return;
    int c = i / HWpad, p = i - c * HWpad;
    float v[8];
    if (p + 8 <= HW) {
        const float* s = S.x[lvl] + (size_t)n * C * HW + (size_t)c * HW + p;
        *(float4*)&v[0] = *(const float4*)s;
        *(float4*)&v[4] = *(const float4*)(s + 4);
    } else {
#pragma unroll
        for (int j = 0; j < 8; j++) v[j] = 0.f;
    }
    size_t o = (size_t)n * tot + i;
    split8(v, (uint4*)(S.xa[lvl] + o), (uint4*)(S.xb[lvl] + o));
}

// ---------------- mma.sync bf16 helpers -------------------------------------------
__device__ __forceinline__ uint32_t smem_u32(const void* p)
{
    uint32_t a;
    asm("{ .reg .u64 t; cvta.to.shared.u64 t, %1; cvt.u32.u64 %0, t; }" : "=r"(a) : "l"(p));
    return a;
}

__device__ __forceinline__ void ldm_x4(uint32_t* r, uint32_t addr)
{
    asm volatile("ldmatrix.sync.aligned.m8n8.x4.shared.b16 {%0,%1,%2,%3}, [%4];"
                 : "=r"(r[0]), "=r"(r[1]), "=r"(r[2]), "=r"(r[3]) : "r"(addr));
}

__device__ __forceinline__ void ldm_x4t(uint32_t* r, uint32_t addr)
{
    asm volatile("ldmatrix.sync.aligned.m8n8.x4.trans.shared.b16 {%0,%1,%2,%3}, [%4];"
                 : "=r"(r[0]), "=r"(r[1]), "=r"(r[2]), "=r"(r[3]) : "r"(addr));
}

__device__ __forceinline__ void mma16(float* c, const uint32_t* a, const uint32_t* b)
{
    asm volatile(
        "mma.sync.aligned.m16n8k16.row.col.f32.bf16.bf16.f32 "
        "{%0,%1,%2,%3}, {%4,%5,%6,%7}, {%8,%9}, {%0,%1,%2,%3};"
        : "+f"(c[0]), "+f"(c[1]), "+f"(c[2]), "+f"(c[3])
        : "r"(a[0]), "r"(a[1]), "r"(a[2]), "r"(a[3]), "r"(b[0]), "r"(b[1]));
}

__device__ __forceinline__ void cpa16(uint32_t dst, const void* src)
{
    asm volatile("cp.async.ca.shared.global [%0], [%1], 16;" :: "r"(dst), "l"(src));
}

__device__ __forceinline__ float silu(float y) { return y / (1.0f + expf(-y)); }

// packed f32x2 fma: d = a*b + d (per 32-bit lane)
__device__ __forceinline__ void fma2(uint64_t& d, uint64_t a, uint64_t b)
{
    asm("fma.rn.f32x2 %0, %1, %2, %0;" : "+l"(d) : "l"(a), "l"(b));
}

__device__ __forceinline__ float2 unpk(uint64_t v)
{
    float2 f;
    asm("mov.b64 {%0,%1}, %2;" : "=f"(f.x), "=f"(f.y) : "l"(v));
    return f;
}

// ---------------- conv: bf16 3-term mma.sync, 3-stage pipeline (R8) ---------------
struct ConvTC {
    const __nv_bfloat16 *wa[3], *wb[3], *xa[3], *xb[3];
    const float *gg[3], *bb[3], *mm[3], *vv[3];
    float *pf[3];
};

__global__ void __launch_bounds__(256, 2) conv_bf16_kernel(ConvTC P)
{
    int n = blockIdx.z;
    if (!g_needed[n]) return;

    int bx = blockIdx.x, lvl, p0, d0;
    if (bx < 50)      { lvl = 0; p0 = bx * 128; d0 = 0; }
    else if (bx < 76) { int r = bx - 50; lvl = 1; p0 = (r % 13) * 128; d0 = (r / 13) * 128; }
    else              { int r = bx - 76; lvl = 2; p0 = (r & 3) * 128;  d0 = (r >> 2) * 128; }
    const int C     = 128 << lvl;
    const int HW    = 6400 >> (2 * lvl);
    const int HWpad = (lvl == 0) ? 6400 : (lvl == 1 ? 1664 : 512);
    const int NC    = C >> 5;

    extern __shared__ uint32_t dsm[];
    const int tid  = threadIdx.x;
    const int lane = tid & 31;
    const int wid  = tid >> 5;
    const int m_off = (wid & 1) * 64;
    const int n_off = (wid >> 1) * 32;
    const int g  = lane >> 2;
    const int tg = lane & 3;
    const uint32_t smb = smem_u32(dsm);

    const __nv_bfloat16* wA1 = P.wa[lvl] + (size_t)d0 * C;
    const __nv_bfloat16* wA2 = P.wb[lvl] + (size_t)d0 * C;
    const __nv_bfloat16* xB1 = P.xa[lvl] + (size_t)n * C * HWpad + p0;
    const __nv_bfloat16* xB2 = P.xb[lvl] + (size_t)n * C * HWpad + p0;

    float acc[4][4][4];
#pragma unroll
    for (int mi = 0; mi < 4; mi++)
#pragma unroll
        for (int ni = 0; ni < 4; ni++)
#pragma unroll
            for (int r = 0; r < 4; r++) acc[mi][ni][r] = 0.f;

    const int ar0 = tid >> 2,          acb0 = tid & 3;
    const int ar1 = (tid + 256) >> 2,  acb1 = (tid + 256) & 3;
    const int br0 = tid >> 4,          bnb0 = tid & 15;
    const int br1 = (tid + 256) >> 4,  bnb1 = (tid + 256) & 15;
    const uint32_t adof0 = ar0 * 64 + ((acb0 ^ ((ar0 >> 1) & 3)) << 4);
    const uint32_t adof1 = ar1 * 64 + ((acb1 ^ ((ar1 >> 1) & 3)) << 4);
    const uint32_t bdof0 = br0 * 256 + ((bnb0 ^ (br0 & 7)) << 4);
    const uint32_t bdof1 = br1 * 256 + ((bnb1 ^ (br1 & 7)) << 4);

#define STAGE(BUF, KC)                                                              \
    do {                                                                            \
        int k0_ = (KC) * 32;                                                        \
        uint32_t bbuf = smb + (BUF) * 32768;                                        \
        cpa16(bbuf + adof0,         wA1 + (size_t)ar0 * C + k0_ + acb0 * 8);        \
        cpa16(bbuf + adof1,         wA1 + (size_t)ar1 * C + k0_ + acb1 * 8);        \
        cpa16(bbuf + 8192 + adof0,  wA2 + (size_t)ar0 * C + k0_ + acb0 * 8);        \
        cpa16(bbuf + 8192 + adof1,  wA2 + (size_t)ar1 * C + k0_ + acb1 * 8);        \
        cpa16(bbuf + 16384 + bdof0, xB1 + (size_t)(k0_ + br0) * HWpad + bnb0 * 8);  \
        cpa16(bbuf + 16384 + bdof1, xB1 + (size_t)(k0_ + br1) * HWpad + bnb1 * 8);  \
        cpa16(bbuf + 24576 + bdof0, xB2 + (size_t)(k0_ + br0) * HWpad + bnb0 * 8);  \
        cpa16(bbuf + 24576 + bdof1, xB2 + (size_t)(k0_ + br1) * HWpad + bnb1 * 8);  \
        asm volatile("cp.async.commit_group;");                                     \
    } while (0)

    STAGE(0, 0);
    STAGE(1, 1);

    int cur = 0;
    for (int kc = 0; kc < NC; kc++) {
        if (kc + 1 < NC) {
            asm volatile("cp.async.wait_group 1;");
        } else {
            asm volatile("cp.async.wait_group 0;");
        }
        __syncthreads();

        if (kc + 2 < NC) {
            int nb = cur + 2;
            if (nb >= 3) nb -= 3;
            STAGE(nb, kc + 2);
        }

        uint32_t base = smb + cur * 32768;
#pragma unroll
        for (int ks = 0; ks < 2; ks++) {
            uint32_t bhf[2][4], blf[2][4];
            int brow = ks * 16 + (lane & 15);
            int nbb  = (n_off >> 3) + (lane >> 4);
#pragma unroll
            for (int nip = 0; nip < 2; nip++) {
                uint32_t boff = brow * 256 + (((nbb + nip * 2) ^ (brow & 7)) << 4);
                ldm_x4t(bhf[nip], base + 16384 + boff);
                ldm_x4t(blf[nip], base + 24576 + boff);
            }
#pragma unroll
            for (int mi = 0; mi < 4; mi++) {
                int arow = m_off + mi * 16 + (lane & 15);
                int cb   = ks * 2 + (lane >> 4);
                uint32_t aoff = arow * 64 + ((cb ^ ((arow >> 1) & 3)) << 4);
                uint32_t ah[4], al[4];
                ldm_x4(ah, base + aoff);
                ldm_x4(al, base + 8192 + aoff);
#pragma unroll
                for (int ni = 0; ni < 4; ni++) {
                    const uint32_t* bh = &bhf[ni >> 1][(ni & 1) * 2];
                    const uint32_t* bl = &blf[ni >> 1][(ni & 1) * 2];
                    mma16(acc[mi][ni], ah, bh);
                    mma16(acc[mi][ni], ah, bl);
                    mma16(acc[mi][ni], al, bh);
                }
            }
        }
        cur = (cur + 1 == 3) ? 0 : cur + 1;
    }

    const float* gg  = P.gg[lvl];
    const float* bbp = P.bb[lvl];
    const float* mm  = P.mm[lvl];
    const float* vv  = P.vv[lvl];
    float*       pf  = P.pf[lvl];
#pragma unroll
    for (int mi = 0; mi < 4; mi++) {
        int r0 = d0 + m_off + mi * 16 + g;
        int r1 = r0 + 8;
        float sc0 = gg[r0] * (1.0f / sqrtf(vv[r0] + 1e-5f));
        float bi0 = bbp[r0] - mm[r0] * sc0;
        float sc1 = gg[r1] * (1.0f / sqrtf(vv[r1] + 1e-5f));
        float bi1 = bbp[r1] - mm[r1] * sc1;
        float* op0 = pf + ((size_t)n * C + r0) * HW;
        float* op1 = pf + ((size_t)n * C + r1) * HW;
#pragma unroll
        for (int ni = 0; ni < 4; ni++) {
            int p = p0 + n_off + ni * 8 + 2 * tg;
            if (p < HW) {
                *(float2*)(op0 + p) = make_float2(silu(acc[mi][ni][0] * sc0 + bi0),
                                                  silu(acc[mi][ni][1] * sc0 + bi0));
                *(float2*)(op1 + p) = make_float2(silu(acc[mi][ni][2] * sc1 + bi1),
                                                  silu(acc[mi][ni][3] * sc1 + bi1));
            }
        }
    }
}

// ---------------- corr: packed f32x2 ----------------------------------------------
// MODE 0: strided packed (STEP=4, lvl0)   MODE 1: window packed (STEP=2, lvl1)
// MODE 2: scalar window WINL=12 (STEP=1, lvl2)
template<int C, int H, int W, int STEP, int NG, int NT, int MODE>
__global__ void __launch_bounds__(NT) corr2_kernel(
    const float* __restrict__ pf, const float* __restrict__ mlpw,
    float* __restrict__ out, int out_off)
{
    constexpr int PAD = RAD * STEP;
    constexpr int W2  = W + 2 * PAD;
    constexpr int H2  = H + 2 * PAD;
    constexpr int HW  = H * W;
    constexpr int NW  = NT / 32;

    extern __shared__ float sm[];
    float* f1p  = sm;
    float* wred = sm + H2 * W2;

    const int c    = blockIdx.x;
    const int b    = blockIdx.y;
    const int n1   = b * TPP + (TPP - 1);
    const int n2a  = g_idx[b * TFF + 0];
    const int n2b  = g_idx[b * TFF + 1];
    const int tid  = threadIdx.x;
    const int wid  = tid >> 5;
    const int lane = tid & 31;

    const float* f1g = pf + ((size_t)n1  * C + c) * HW;
    const float* f2a = pf + ((size_t)n2a * C + c) * HW;
    const float* f2b = pf + ((size_t)n2b * C + c) * HW;

    for (int q = tid; q < H2 * W2; q += NT) {
        int hh = q / W2 - PAD;
        int ww = q % W2 - PAD;
        float v = 0.f;
        if ((unsigned)hh < (unsigned)H && (unsigned)ww < (unsigned)W)
            v = f1g[hh * W + ww];
        f1p[q] = v;
    }

    if (MODE == 0 || MODE == 1) {
        // packed f2: [gi][0]={px0,px1}, [gi][1]={px2,px3}
        uint64_t fpa[NG][2], fpb[NG][2];
        int basek[NG];
#pragma unroll
        for (int gi = 0; gi < NG; gi++) {
            int p = (tid + NT * gi) * 4;
            if (p < HW) {
                fpa[gi][0] = *(const uint64_t*)(f2a + p);
                fpa[gi][1] = *(const uint64_t*)(f2a + p + 2);
                fpb[gi][0] = *(const uint64_t*)(f2b + p);
                fpb[gi][1] = *(const uint64_t*)(f2b + p + 2);
                basek[gi] = (p / W + PAD) * W2 + (p % W) + PAD;
            } else {
                fpa[gi][0] = fpa[gi][1] = 0ull;
                fpb[gi][0] = fpb[gi][1] = 0ull;
                basek[gi] = PAD * W2 + PAD;
            }
        }
        __syncthreads();

        if (MODE == 0) {
            for (int oy = 0; oy < 9; oy++) {
                int ro[NG];
                int dyo = (oy - RAD) * STEP * W2;
#pragma unroll
                for (int gi = 0; gi < NG; gi++) ro[gi] = basek[gi] + dyo;
#pragma unroll
                for (int ox = 0; ox < 9; ox++) {
                    const int dxo = (ox - RAD) * STEP;
                    uint64_t A0 = 0ull, A1 = 0ull, B0 = 0ull, B1 = 0ull;
#pragma unroll
                    for (int gi = 0; gi < NG; gi++) {
                        const float* p = &f1p[ro[gi] + dxo];
                        uint64_t f01 = *(const uint64_t*)p;
                        uint64_t f23 = *(const uint64_t*)(p + 2);
                        fma2(A0, f01, fpa[gi][0]);
                        fma2(A1, f23, fpa[gi][1]);
                        fma2(B0, f01, fpb[gi][0]);
                        fma2(B1, f23, fpb[gi][1]);
                    }
                    float2 a0 = unpk(A0), a1 = unpk(A1);
                    float2 b0 = unpk(B0), b1 = unpk(B1);
                    float va = (a0.x + a0.y) + (a1.x + a1.y);
                    float vb = (b0.x + b0.y) + (b1.x + b1.y);
#pragma unroll
                    for (int o = 16; o; o >>= 1) {
                        va += __shfl_xor_sync(0xffffffffu, va, o);
                        vb += __shfl_xor_sync(0xffffffffu, vb, o);
                    }
                    if (lane == 0) {
                        wred[(0 * NW + wid) * NS + oy * 9 + ox] = va;
                        wred[(1 * NW + wid) * NS + oy * 9 + ox] = vb;
                    }
                }
            }
        } else {
            // MODE 1: window packed. STEP=2, window of 20 floats = 10 b64.
            for (int oy = 0; oy < 9; oy++) {
                int dyo = (oy - RAD) * STEP * W2;
                uint64_t accA[9], accB[9];
#pragma unroll
                for (int ox = 0; ox < 9; ox++) { accA[ox] = 0ull; accB[ox] = 0ull; }
#pragma unroll
                for (int gi = 0; gi < NG; gi++) {
                    const float* wp = &f1p[basek[gi] + dyo - 4 * STEP];
                    uint64_t w2[10];
#pragma unroll
                    for (int t = 0; t < 10; t++)
                        w2[t] = *(const uint64_t*)(wp + 2 * t);
#pragma unroll
                    for (int ox = 0; ox < 9; ox++) {
                        fma2(accA[ox], w2[ox],     fpa[gi][0]);
                        fma2(accA[ox], w2[ox + 1], fpa[gi][1]);
                        fma2(accB[ox], w2[ox],     fpb[gi][0]);
                        fma2(accB[ox], w2[ox + 1], fpb[gi][1]);
                    }
                }
#pragma unroll
                for (int ox = 0; ox < 9; ox++) {
                    float2 a = unpk(accA[ox]), bq = unpk(accB[ox]);
                    float va = a.x + a.y, vb = bq.x + bq.y;
#pragma unroll
                    for (int o = 16; o; o >>= 1) {
                        va += __shfl_xor_sync(0xffffffffu, va, o);
                        vb += __shfl_xor_sync(0xffffffffu, vb, o);
                    }
                    if (lane == 0) {
                        wred[(0 * NW + wid) * NS + oy * 9 + ox] = va;
                        wred[(1 * NW + wid) * NS + oy * 9 + ox] = vb;
                    }
                }
            }
        }
    } else {
        // MODE 2: scalar window (STEP=1, WINL=12)
        constexpr int WINL = 12;
        float fra[NG][4], frb[NG][4];
        int   basek[NG];
#pragma unroll
        for (int gi = 0; gi < NG; gi++) {
            int p = (tid + NT * gi) * 4;
            if (p < HW) {
                float4 va = *(const float4*)(f2a + p);
                float4 vb = *(const float4*)(f2b + p);
                fra[gi][0] = va.x; fra[gi][1] = va.y; fra[gi][2] = va.z; fra[gi][3] = va.w;
                frb[gi][0] = vb.x; frb[gi][1] = vb.y; frb[gi][2] = vb.z; frb[gi][3] = vb.w;
                basek[gi] = (p / W + PAD) * W2 + (p % W) + PAD;
            } else {
#pragma unroll
                for (int v = 0; v < 4; v++) { fra[gi][v] = 0.f; frb[gi][v] = 0.f; }
                basek[gi] = PAD * W2 + PAD;
            }
        }
        __syncthreads();

        for (int oy = 0; oy < 9; oy++) {
            int dyo = (oy - RAD) * STEP * W2;
            float aA[9], aB[9];
#pragma unroll
            for (int ox = 0; ox < 9; ox++) { aA[ox] = 0.f; aB[ox] = 0.f; }
#pragma unroll
            for (int gi = 0; gi < NG; gi++) {
                const float* wp = &f1p[basek[gi] + dyo - 4 * STEP];
                float win[WINL];
#pragma unroll
                for (int t = 0; t < WINL / 4; t++) {
                    float4 v = *(const float4*)(wp + 4 * t);
                    win[4 * t] = v.x; win[4 * t + 1] = v.y;
                    win[4 * t + 2] = v.z; win[4 * t + 3] = v.w;
                }
#pragma unroll
                for (int ox = 0; ox < 9; ox++) {
#pragma unroll
                    for (int j = 0; j < 4; j++) {
                        aA[ox] = fmaf(win[STEP * ox + j], fra[gi][j], aA[ox]);
                        aB[ox] = fmaf(win[STEP * ox + j], frb[gi][j], aB[ox]);
                    }
                }
            }
#pragma unroll
            for (int ox = 0; ox < 9; ox++) {
                float va = aA[ox], vb = aB[ox];
#pragma unroll
                for (int o = 16; o; o >>= 1) {
                    va += __shfl_xor_sync(0xffffffffu, va, o);
                    vb += __shfl_xor_sync(0xffffffffu, vb, o);
                }
                if (lane == 0) {
                    wred[(0 * NW + wid) * NS + oy * 9 + ox] = va;
                    wred[(1 * NW + wid) * NS + oy * 9 + ox] = vb;
                }
            }
        }
    }
    __syncthreads();

    if (tid < 64) {
        int q = tid >> 5, l = tid & 31;
        const float* wr = wred + q * NW * NS;
        float v0, v1 = -1e30f, v2 = -1e30f;
        {
            float s0 = 0.f, s1 = 0.f, s2 = 0.f;
#pragma unroll
            for (int w = 0; w < NW; w++) {
                s0 += wr[w * NS + l];
                if (l + 32 < NS) s1 += wr[w * NS + l + 32];
                if (l + 64 < NS) s2 += wr[w * NS + l + 64];
            }
            v0 = s0;
            if (l + 32 < NS) v1 = s1;
            if (l + 64 < NS) v2 = s2;
        }
        float mx = fmaxf(v0, fmaxf(v1, v2));
#pragma unroll
        for (int o = 16; o; o >>= 1)
            mx = fmaxf(mx, __shfl_xor_sync(0xffffffffu, mx, o));
        float e0 = expf(v0 - mx);
        float e1 = (l + 32 < NS) ? expf(v1 - mx) : 0.f;
        float e2 = (l + 64 < NS) ? expf(v2 - mx) : 0.f;
        float w0 = mlpw[l];
        float w1 = (l + 32 < NS) ? mlpw[l + 32] : 0.f;
        float w2 = (l + 64 < NS) ? mlpw[l + 64] : 0.f;
        float ssum = e0 + e1 + e2;
        float dot  = e0 * w0 + e1 * w1 + e2 * w2;
#pragma unroll
        for (int o = 16; o; o >>= 1) {
            ssum += __shfl_xor_sync(0xffffffffu, ssum, o);
            dot  += __shfl_xor_sync(0xffffffffu, dot,  o);
        }
        if (l == 0)
            out[out_off + (b * TFF + q) * C + c] = dot / ssum;
    }
}

// ---------------- launch ----------------------------------------------------------
extern "C" void kernel_launch(void* const* d_in, const int* in_sizes, int n_in,
                              void* d_out, int out_size)
{
    int map_sig [21] = {0,1,2, 3,4,5,6,7, 8,9,10,11,12, 13,14,15,16,17, 18,19,20};
    int map_dict[21] = {0,6,12, 1,2,3,4,5, 7,8,9,10,11, 13,14,15,16,17, 18,19,20};
    const int* map = (in_sizes[1] == 16384) ? map_dict : map_sig;

    const float* mlpw = (const float*)d_in[map[18]];
    const int*   pci  = (const int*)d_in[map[19]];
    const int*   fci  = (const int*)d_in[map[20]];
    float* out = (float*)d_out;

    void* pv;
    cudaGetSymbolAddress(&pv, g_pf0);  float* pf0 = (float*)pv;
    cudaGetSymbolAddress(&pv, g_pf1);  float* pf1 = (float*)pv;
    cudaGetSymbolAddress(&pv, g_pf2);  float* pf2 = (float*)pv;
    __nv_bfloat16 *w0a, *w0b, *w1a, *w1b, *w2a, *w2b;
    __nv_bfloat16 *x0a, *x0b, *x1a, *x1b, *x2a, *x2b;
    cudaGetSymbolAddress(&pv, g_w0a); w0a = (__nv_bfloat16*)pv;
    cudaGetSymbolAddress(&pv, g_w0b); w0b = (__nv_bfloat16*)pv;
    cudaGetSymbolAddress(&pv, g_w1a); w1a = (__nv_bfloat16*)pv;
    cudaGetSymbolAddress(&pv, g_w1b); w1b = (__nv_bfloat16*)pv;
    cudaGetSymbolAddress(&pv, g_w2a); w2a = (__nv_bfloat16*)pv;
    cudaGetSymbolAddress(&pv, g_w2b); w2b = (__nv_bfloat16*)pv;
    cudaGetSymbolAddress(&pv, g_x0a); x0a = (__nv_bfloat16*)pv;
    cudaGetSymbolAddress(&pv, g_x0b); x0b = (__nv_bfloat16*)pv;
    cudaGetSymbolAddress(&pv, g_x1a); x1a = (__nv_bfloat16*)pv;
    cudaGetSymbolAddress(&pv, g_x1b); x1b = (__nv_bfloat16*)pv;
    cudaGetSymbolAddress(&pv, g_x2a); x2a = (__nv_bfloat16*)pv;
    cudaGetSymbolAddress(&pv, g_x2b); x2b = (__nv_bfloat16*)pv;

    prep_kernel<<<1, 1>>>(pci, fci);

    SplitW SW;
    SW.w[0] = (const float*)d_in[map[3]];
    SW.w[1] = (const float*)d_in[map[8]];
    SW.w[2] = (const float*)d_in[map[13]];
    SW.wa[0] = w0a; SW.wa[1] = w1a; SW.wa[2] = w2a;
    SW.wb[0] = w0b; SW.wb[1] = w1b; SW.wb[2] = w2b;
    wsplit_all<<<dim3(128, 3), 256>>>(SW);   // max: 512*512/8/256 = 128 blocks

    SplitX SX;
    SX.x[0] = (const float*)d_in[map[0]];
    SX.x[1] = (const float*)d_in[map[1]];
    SX.x[2] = (const float*)d_in[map[2]];
    SX.xa[0] = x0a; SX.xa[1] = x1a; SX.xa[2] = x2a;
    SX.xb[0] = x0b; SX.xb[1] = x1b; SX.xb[2] = x2b;
    xsplit_all<<<dim3(400, 3, NFR), 256>>>(SX);  // max: 128*6400/8/256 = 400

    ConvTC P;
    P.wa[0] = w0a; P.wa[1] = w1a; P.wa[2] = w2a;
    P.wb[0] = w0b; P.wb[1] = w1b; P.wb[2] = w2b;
    P.xa[0] = x0a; P.xa[1] = x1a; P.xa[2] = x2a;
    P.xb[0] = x0b; P.xb[1] = x1b; P.xb[2] = x2b;
    P.gg[0] = (const float*)d_in[map[4]];  P.gg[1] = (const float*)d_in[map[9]];   P.gg[2] = (const float*)d_in[map[14]];
    P.bb[0] = (const float*)d_in[map[5]];  P.bb[1] = (const float*)d_in[map[10]];  P.bb[2] = (const float*)d_in[map[15]];
    P.mm[0] = (const float*)d_in[map[6]];  P.mm[1] = (const float*)d_in[map[11]];  P.mm[2] = (const float*)d_in[map[16]];
    P.vv[0] = (const float*)d_in[map[7]];  P.vv[1] = (const float*)d_in[map[12]];  P.vv[2] = (const float*)d_in[map[17]];
    P.pf[0] = pf0; P.pf[1] = pf1; P.pf[2] = pf2;

    cudaFuncSetAttribute(conv_bf16_kernel,
                         cudaFuncAttributeMaxDynamicSharedMemorySize, 3 * 32768);
    conv_bf16_kernel<<<dim3(92, 1, NFR), 256, 3 * 32768>>>(P);

    size_t sm0 = (size_t)(112 * 112 + 2 * 8 * NS) * sizeof(float);
    size_t sm1 = (size_t)( 56 *  56 + 2 * 8 * NS) * sizeof(float);
    size_t sm2 = (size_t)( 28 *  28 + 2 * 4 * NS) * sizeof(float);
    cudaFuncSetAttribute((const void*)corr2_kernel<128, 80, 80, 4, 7, 256, 0>,
                         cudaFuncAttributeMaxDynamicSharedMemorySize, 65536);

    corr2_kernel<128, 80, 80, 4, 7, 256, 0><<<dim3(128, BB), 256, sm0>>>(pf0, mlpw, out, 0);
    corr2_kernel<256, 40, 40, 2, 2, 256, 1><<<dim3(256, BB), 256, sm1>>>(pf1, mlpw, out, 1024);
    corr2_kernel<512, 20, 20, 1, 1, 128, 2><<<dim3(512, BB), 128, sm2>>>(pf2, mlpw, out, 3072);
}

// round 10
// speedup vs baseline: 1.0464x; 1.0464x over previous
#include <cuda_runtime.h>
#include <cuda_bf16.h>
#include <math.h>
#include <stdint.h>

#define BB    4
#define TPP   4
#define TFF   2
#define NPAIR (BB*TFF)
#define RAD   4
#define NS    81
#define NFR   (BB*TPP)

// ---------------- scratch ---------------------------------------------------------
__device__ int   g_idx[NPAIR];
__device__ int   g_needed[NFR];
__device__ float g_pf0[(size_t)NFR * 128 * 6400];
__device__ float g_pf1[(size_t)NFR * 256 * 1600];
__device__ float g_pf2[(size_t)NFR * 512 * 400];
__device__ __nv_bfloat16 g_w0a[128*128],  g_w0b[128*128];
__device__ __nv_bfloat16 g_w1a[256*256],  g_w1b[256*256];
__device__ __nv_bfloat16 g_w2a[512*512],  g_w2b[512*512];
__device__ __nv_bfloat16 g_x0a[(size_t)NFR*128*6400], g_x0b[(size_t)NFR*128*6400];
__device__ __nv_bfloat16 g_x1a[(size_t)NFR*256*1664], g_x1b[(size_t)NFR*256*1664];
__device__ __nv_bfloat16 g_x2a[(size_t)NFR*512*512],  g_x2b[(size_t)NFR*512*512];

// ---------------- prep ------------------------------------------------------------
__global__ void prep_kernel(const int* __restrict__ pci, const int* __restrict__ fci)
{
    if (threadIdx.x != 0 || blockIdx.x != 0) return;
    for (int n = 0; n < NFR; n++) g_needed[n] = 0;
    for (int i = 0; i < BB; i++) {
        int p_pos = TPP - 2;
        for (int j = 0; j < TFF; j++) {
            int f_i = fci[i * TFF + j];
            while (p_pos >= 0) {
                if (p_pos == 0 || f_i < -pci[i * TPP + p_pos - 1]) {
                    int id = p_pos + i * TPP;
                    g_idx[i * TFF + j] = id;
                    g_needed[id] = 1;
                    break;
                }
                p_pos--;
            }
        }
        g_needed[i * TPP + (TPP - 1)] = 1;
    }
}

// ---------------- fused split kernels ---------------------------------------------
union BV8 { __nv_bfloat16 h[8]; uint4 u; };

__device__ __forceinline__ void split8(const float* v, uint4* ua, uint4* ub)
{
    BV8 a, b;
#pragma unroll
    for (int j = 0; j < 8; j++) {
        __nv_bfloat16 h = __float2bfloat16(v[j]);
        a.h[j] = h;
        b.h[j] = __float2bfloat16(v[j] - __bfloat162float(h));
    }
    *ua = a.u; *ub = b.u;
}

struct SplitW {
    const float* w[3];
    __nv_bfloat16 *wa[3], *wb[3];
};

__global__ void wsplit_all(SplitW S)
{
    int lvl = blockIdx.y;
    int nE  = (128 << lvl) * (128 << lvl);
    int i   = (blockIdx.x * 256 + threadIdx.x) * 8;
    if (i < nE) {
        float v[8];
        *(float4*)&v[0] = *(const float4*)(S.w[lvl] + i);
        *(float4*)&v[4] = *(const float4*)(S.w[lvl] + i + 4);
        split8(v, (uint4*)(S.wa[lvl] + i), (uint4*)(S.wb[lvl] + i));
    }
}

struct SplitX {
    const float* x[3];
    __nv_bfloat16 *xa[3], *xb[3];
};

__global__ void xsplit_all(SplitX S)
{
    int n = blockIdx.z;
    if (!g_needed[n]) return;
    int lvl = blockIdx.y;
    const int C     = 128 << lvl;
    const int HW    = 6400 >> (2 * lvl);
    const int HWpad = (lvl == 0) ? 6400 : (lvl == 1 ? 1664 : 512);
    int tot = C * HWpad;
    int i = (blockIdx.x * 256 + threadIdx.x) * 8;
    if (i >= tot) return;
    int c = i / HWpad, p = i - c * HWpad;
    float v[8];
    if (p + 8 <= HW) {
        const float* s = S.x[lvl] + (size_t)n * C * HW + (size_t)c * HW + p;
        *(float4*)&v[0] = *(const float4*)s;
        *(float4*)&v[4] = *(const float4*)(s + 4);
    } else {
#pragma unroll
        for (int j = 0; j < 8; j++) v[j] = 0.f;
    }
    size_t o = (size_t)n * tot + i;
    split8(v, (uint4*)(S.xa[lvl] + o), (uint4*)(S.xb[lvl] + o));
}

// ---------------- mma.sync bf16 helpers -------------------------------------------
__device__ __forceinline__ uint32_t smem_u32(const void* p)
{
    uint32_t a;
    asm("{ .reg .u64 t; cvta.to.shared.u64 t, %1; cvt.u32.u64 %0, t; }" : "=r"(a) : "l"(p));
    return a;
}

__device__ __forceinline__ void ldm_x4(uint32_t* r, uint32_t addr)
{
    asm volatile("ldmatrix.sync.aligned.m8n8.x4.shared.b16 {%0,%1,%2,%3}, [%4];"
                 : "=r"(r[0]), "=r"(r[1]), "=r"(r[2]), "=r"(r[3]) : "r"(addr));
}

__device__ __forceinline__ void ldm_x4t(uint32_t* r, uint32_t addr)
{
    asm volatile("ldmatrix.sync.aligned.m8n8.x4.trans.shared.b16 {%0,%1,%2,%3}, [%4];"
                 : "=r"(r[0]), "=r"(r[1]), "=r"(r[2]), "=r"(r[3]) : "r"(addr));
}

__device__ __forceinline__ void mma16(float* c, const uint32_t* a, const uint32_t* b)
{
    asm volatile(
        "mma.sync.aligned.m16n8k16.row.col.f32.bf16.bf16.f32 "
        "{%0,%1,%2,%3}, {%4,%5,%6,%7}, {%8,%9}, {%0,%1,%2,%3};"
        : "+f"(c[0]), "+f"(c[1]), "+f"(c[2]), "+f"(c[3])
        : "r"(a[0]), "r"(a[1]), "r"(a[2]), "r"(a[3]), "r"(b[0]), "r"(b[1]));
}

__device__ __forceinline__ void cpa16(uint32_t dst, const void* src)
{
    asm volatile("cp.async.cg.shared.global [%0], [%1], 16;" :: "r"(dst), "l"(src));
}

__device__ __forceinline__ float silu(float y) { return y / (1.0f + expf(-y)); }

// ---------------- conv: bf16 3-term mma.sync, 3-stage pipeline --------------------
struct ConvTC {
    const __nv_bfloat16 *wa[3], *wb[3], *xa[3], *xb[3];
    const float *gg[3], *bb[3], *mm[3], *vv[3];
    float *pf[3];
};

__global__ void __launch_bounds__(256, 2) conv_bf16_kernel(ConvTC P)
{
    int n = blockIdx.z;
    if (!g_needed[n]) return;

    int bx = blockIdx.x, lvl, p0, d0;
    if (bx < 50)      { lvl = 0; p0 = bx * 128; d0 = 0; }
    else if (bx < 76) { int r = bx - 50; lvl = 1; p0 = (r % 13) * 128; d0 = (r / 13) * 128; }
    else              { int r = bx - 76; lvl = 2; p0 = (r & 3) * 128;  d0 = (r >> 2) * 128; }
    const int C     = 128 << lvl;
    const int HW    = 6400 >> (2 * lvl);
    const int HWpad = (lvl == 0) ? 6400 : (lvl == 1 ? 1664 : 512);
    const int NC    = C >> 5;

    extern __shared__ uint32_t dsm[];
    const int tid  = threadIdx.x;
    const int lane = tid & 31;
    const int wid  = tid >> 5;
    const int m_off = (wid & 1) * 64;
    const int n_off = (wid >> 1) * 32;
    const int g  = lane >> 2;
    const int tg = lane & 3;
    const uint32_t smb = smem_u32(dsm);

    const __nv_bfloat16* wA1 = P.wa[lvl] + (size_t)d0 * C;
    const __nv_bfloat16* wA2 = P.wb[lvl] + (size_t)d0 * C;
    const __nv_bfloat16* xB1 = P.xa[lvl] + (size_t)n * C * HWpad + p0;
    const __nv_bfloat16* xB2 = P.xb[lvl] + (size_t)n * C * HWpad + p0;

    float acc[4][4][4];
#pragma unroll
    for (int mi = 0; mi < 4; mi++)
#pragma unroll
        for (int ni = 0; ni < 4; ni++)
#pragma unroll
            for (int r = 0; r < 4; r++) acc[mi][ni][r] = 0.f;

    const int ar0 = tid >> 2,          acb0 = tid & 3;
    const int ar1 = (tid + 256) >> 2,  acb1 = (tid + 256) & 3;
    const int br0 = tid >> 4,          bnb0 = tid & 15;
    const int br1 = (tid + 256) >> 4,  bnb1 = (tid + 256) & 15;
    const uint32_t adof0 = ar0 * 64 + ((acb0 ^ ((ar0 >> 1) & 3)) << 4);
    const uint32_t adof1 = ar1 * 64 + ((acb1 ^ ((ar1 >> 1) & 3)) << 4);
    const uint32_t bdof0 = br0 * 256 + ((bnb0 ^ (br0 & 7)) << 4);
    const uint32_t bdof1 = br1 * 256 + ((bnb1 ^ (br1 & 7)) << 4);

#define STAGE(BUF, KC)                                                              \
    do {                                                                            \
        int k0_ = (KC) * 32;                                                        \
        uint32_t bbuf = smb + (BUF) * 32768;                                        \
        cpa16(bbuf + adof0,         wA1 + (size_t)ar0 * C + k0_ + acb0 * 8);        \
        cpa16(bbuf + adof1,         wA1 + (size_t)ar1 * C + k0_ + acb1 * 8);        \
        cpa16(bbuf + 8192 + adof0,  wA2 + (size_t)ar0 * C + k0_ + acb0 * 8);        \
        cpa16(bbuf + 8192 + adof1,  wA2 + (size_t)ar1 * C + k0_ + acb1 * 8);        \
        cpa16(bbuf + 16384 + bdof0, xB1 + (size_t)(k0_ + br0) * HWpad + bnb0 * 8);  \
        cpa16(bbuf + 16384 + bdof1, xB1 + (size_t)(k0_ + br1) * HWpad + bnb1 * 8);  \
        cpa16(bbuf + 24576 + bdof0, xB2 + (size_t)(k0_ + br0) * HWpad + bnb0 * 8);  \
        cpa16(bbuf + 24576 + bdof1, xB2 + (size_t)(k0_ + br1) * HWpad + bnb1 * 8);  \
        asm volatile("cp.async.commit_group;");                                     \
    } while (0)

    STAGE(0, 0);
    STAGE(1, 1);

    int cur = 0;
    const int ks_xor = wid & 1;     // stagger LDSM bursts across warps
    for (int kc = 0; kc < NC; kc++) {
        if (kc + 1 < NC) {
            asm volatile("cp.async.wait_group 1;");
        } else {
            asm volatile("cp.async.wait_group 0;");
        }
        __syncthreads();

        if (kc + 2 < NC) {
            int nb = cur + 2;
            if (nb >= 3) nb -= 3;
            STAGE(nb, kc + 2);
        }

        uint32_t base = smb + cur * 32768;
#pragma unroll
        for (int ksi = 0; ksi < 2; ksi++) {
            int ks = ksi ^ ks_xor;
            uint32_t bhf[2][4], blf[2][4];
            int brow = ks * 16 + (lane & 15);
            int nbb  = (n_off >> 3) + (lane >> 4);
#pragma unroll
            for (int nip = 0; nip < 2; nip++) {
                uint32_t boff = brow * 256 + (((nbb + nip * 2) ^ (brow & 7)) << 4);
                ldm_x4t(bhf[nip], base + 16384 + boff);
                ldm_x4t(blf[nip], base + 24576 + boff);
            }
#pragma unroll
            for (int mi = 0; mi < 4; mi++) {
                int arow = m_off + mi * 16 + (lane & 15);
                int cb   = ks * 2 + (lane >> 4);
                uint32_t aoff = arow * 64 + ((cb ^ ((arow >> 1) & 3)) << 4);
                uint32_t ah[4], al[4];
                ldm_x4(ah, base + aoff);
                ldm_x4(al, base + 8192 + aoff);
#pragma unroll
                for (int ni = 0; ni < 4; ni++) {
                    const uint32_t* bh = &bhf[ni >> 1][(ni & 1) * 2];
                    const uint32_t* bl = &blf[ni >> 1][(ni & 1) * 2];
                    mma16(acc[mi][ni], ah, bh);
                    mma16(acc[mi][ni], ah, bl);
                    mma16(acc[mi][ni], al, bh);
                }
            }
        }
        cur = (cur + 1 == 3) ? 0 : cur + 1;
    }

    const float* gg  = P.gg[lvl];
    const float* bbp = P.bb[lvl];
    const float* mm  = P.mm[lvl];
    const float* vv  = P.vv[lvl];
    float*       pf  = P.pf[lvl];
#pragma unroll
    for (int mi = 0; mi < 4; mi++) {
        int r0 = d0 + m_off + mi * 16 + g;
        int r1 = r0 + 8;
        float sc0 = gg[r0] * (1.0f / sqrtf(vv[r0] + 1e-5f));
        float bi0 = bbp[r0] - mm[r0] * sc0;
        float sc1 = gg[r1] * (1.0f / sqrtf(vv[r1] + 1e-5f));
        float bi1 = bbp[r1] - mm[r1] * sc1;
        float* op0 = pf + ((size_t)n * C + r0) * HW;
        float* op1 = pf + ((size_t)n * C + r1) * HW;
#pragma unroll
        for (int ni = 0; ni < 4; ni++) {
            int p = p0 + n_off + ni * 8 + 2 * tg;
            if (p < HW) {
                *(float2*)(op0 + p) = make_float2(silu(acc[mi][ni][0] * sc0 + bi0),
                                                  silu(acc[mi][ni][1] * sc0 + bi0));
                *(float2*)(op1 + p) = make_float2(silu(acc[mi][ni][2] * sc1 + bi1),
                                                  silu(acc[mi][ni][3] * sc1 + bi1));
            }
        }
    }
}

// ---------------- corr (R8 known-good) --------------------------------------------
template<int C, int H, int W, int STEP, int NG, int NT, int WINL>
__global__ void __launch_bounds__(NT) corr2_kernel(
    const float* __restrict__ pf, const float* __restrict__ mlpw,
    float* __restrict__ out, int out_off)
{
    constexpr int PAD = RAD * STEP;
    constexpr int W2  = W + 2 * PAD;
    constexpr int H2  = H + 2 * PAD;
    constexpr int HW  = H * W;
    constexpr int NW  = NT / 32;

    extern __shared__ float sm[];
    float* f1p  = sm;
    float* wred = sm + H2 * W2;

    const int c    = blockIdx.x;
    const int b    = blockIdx.y;
    const int n1   = b * TPP + (TPP - 1);
    const int n2a  = g_idx[b * TFF + 0];
    const int n2b  = g_idx[b * TFF + 1];
    const int tid  = threadIdx.x;
    const int wid  = tid >> 5;
    const int lane = tid & 31;

    const float* f1g = pf + ((size_t)n1  * C + c) * HW;
    const float* f2a = pf + ((size_t)n2a * C + c) * HW;
    const float* f2b = pf + ((size_t)n2b * C + c) * HW;

    for (int q = tid; q < H2 * W2; q += NT) {
        int hh = q / W2 - PAD;
        int ww = q % W2 - PAD;
        float v = 0.f;
        if ((unsigned)hh < (unsigned)H && (unsigned)ww < (unsigned)W)
            v = f1g[hh * W + ww];
        f1p[q] = v;
    }

    float fra[NG][4], frb[NG][4];
    int   basek[NG];
#pragma unroll
    for (int gi = 0; gi < NG; gi++) {
        int p = (tid + NT * gi) * 4;
        if (p < HW) {
            float4 va = *(const float4*)(f2a + p);
            float4 vb = *(const float4*)(f2b + p);
            fra[gi][0] = va.x; fra[gi][1] = va.y; fra[gi][2] = va.z; fra[gi][3] = va.w;
            frb[gi][0] = vb.x; frb[gi][1] = vb.y; frb[gi][2] = vb.z; frb[gi][3] = vb.w;
            basek[gi] = (p / W + PAD) * W2 + (p % W) + PAD;
        } else {
#pragma unroll
            for (int v = 0; v < 4; v++) { fra[gi][v] = 0.f; frb[gi][v] = 0.f; }
            basek[gi] = PAD * W2 + PAD;
        }
    }
    __syncthreads();

    if (WINL == 0) {
        for (int oy = 0; oy < 9; oy++) {
            int ro[NG];
            int dyo = (oy - RAD) * STEP * W2;
#pragma unroll
            for (int gi = 0; gi < NG; gi++) ro[gi] = basek[gi] + dyo;
#pragma unroll
            for (int ox = 0; ox < 9; ox++) {
                const int dxo = (ox - RAD) * STEP;
                float a0 = 0.f, a1 = 0.f, b0 = 0.f, b1 = 0.f;
#pragma unroll
                for (int gi = 0; gi < NG; gi++) {
                    float4 fv = *(const float4*)&f1p[ro[gi] + dxo];
                    a0 = fmaf(fv.x, fra[gi][0], a0);
                    a1 = fmaf(fv.y, fra[gi][1], a1);
                    a0 = fmaf(fv.z, fra[gi][2], a0);
                    a1 = fmaf(fv.w, fra[gi][3], a1);
                    b0 = fmaf(fv.x, frb[gi][0], b0);
                    b1 = fmaf(fv.y, frb[gi][1], b1);
                    b0 = fmaf(fv.z, frb[gi][2], b0);
                    b1 = fmaf(fv.w, frb[gi][3], b1);
                }
                float va = a0 + a1, vb = b0 + b1;
#pragma unroll
                for (int o = 16; o; o >>= 1) {
                    va += __shfl_xor_sync(0xffffffffu, va, o);
                    vb += __shfl_xor_sync(0xffffffffu, vb, o);
                }
                if (lane == 0) {
                    wred[(0 * NW + wid) * NS + oy * 9 + ox] = va;
                    wred[(1 * NW + wid) * NS + oy * 9 + ox] = vb;
                }
            }
        }
    } else {
        for (int oy = 0; oy < 9; oy++) {
            int dyo = (oy - RAD) * STEP * W2;
            float aA[9], aB[9];
#pragma unroll
            for (int ox = 0; ox < 9; ox++) { aA[ox] = 0.f; aB[ox] = 0.f; }
#pragma unroll
            for (int gi = 0; gi < NG; gi++) {
                const float* wp = &f1p[basek[gi] + dyo - 4 * STEP];
                float win[WINL > 0 ? WINL : 1];
#pragma unroll
                for (int t = 0; t < WINL / 4; t++) {
                    float4 v = *(const float4*)(wp + 4 * t);
                    win[4 * t] = v.x; win[4 * t + 1] = v.y;
                    win[4 * t + 2] = v.z; win[4 * t + 3] = v.w;
                }
#pragma unroll
                for (int ox = 0; ox < 9; ox++) {
#pragma unroll
                    for (int j = 0; j < 4; j++) {
                        aA[ox] = fmaf(win[STEP * ox + j], fra[gi][j], aA[ox]);
                        aB[ox] = fmaf(win[STEP * ox + j], frb[gi][j], aB[ox]);
                    }
                }
            }
#pragma unroll
            for (int ox = 0; ox < 9; ox++) {
                float va = aA[ox], vb = aB[ox];
#pragma unroll
                for (int o = 16; o; o >>= 1) {
                    va += __shfl_xor_sync(0xffffffffu, va, o);
                    vb += __shfl_xor_sync(0xffffffffu, vb, o);
                }
                if (lane == 0) {
                    wred[(0 * NW + wid) * NS + oy * 9 + ox] = va;
                    wred[(1 * NW + wid) * NS + oy * 9 + ox] = vb;
                }
            }
        }
    }
    __syncthreads();

    if (tid < 64) {
        int q = tid >> 5, l = tid & 31;
        const float* wr = wred + q * NW * NS;
        float v0, v1 = -1e30f, v2 = -1e30f;
        {
            float s0 = 0.f, s1 = 0.f, s2 = 0.f;
#pragma unroll
            for (int w = 0; w < NW; w++) {
                s0 += wr[w * NS + l];
                if (l + 32 < NS) s1 += wr[w * NS + l + 32];
                if (l + 64 < NS) s2 += wr[w * NS + l + 64];
            }
            v0 = s0;
            if (l + 32 < NS) v1 = s1;
            if (l + 64 < NS) v2 = s2;
        }
        float mx = fmaxf(v0, fmaxf(v1, v2));
#pragma unroll
        for (int o = 16; o; o >>= 1)
            mx = fmaxf(mx, __shfl_xor_sync(0xffffffffu, mx, o));
        float e0 = expf(v0 - mx);
        float e1 = (l + 32 < NS) ? expf(v1 - mx) : 0.f;
        float e2 = (l + 64 < NS) ? expf(v2 - mx) : 0.f;
        float w0 = mlpw[l];
        float w1 = (l + 32 < NS) ? mlpw[l + 32] : 0.f;
        float w2 = (l + 64 < NS) ? mlpw[l + 64] : 0.f;
        float ssum = e0 + e1 + e2;
        float dot  = e0 * w0 + e1 * w1 + e2 * w2;
#pragma unroll
        for (int o = 16; o; o >>= 1) {
            ssum += __shfl_xor_sync(0xffffffffu, ssum, o);
            dot  += __shfl_xor_sync(0xffffffffu, dot,  o);
        }
        if (l == 0)
            out[out_off + (b * TFF + q) * C + c] = dot / ssum;
    }
}

// ---------------- launch ----------------------------------------------------------
extern "C" void kernel_launch(void* const* d_in, const int* in_sizes, int n_in,
                              void* d_out, int out_size)
{
    int map_sig [21] = {0,1,2, 3,4,5,6,7, 8,9,10,11,12, 13,14,15,16,17, 18,19,20};
    int map_dict[21] = {0,6,12, 1,2,3,4,5, 7,8,9,10,11, 13,14,15,16,17, 18,19,20};
    const int* map = (in_sizes[1] == 16384) ? map_dict : map_sig;

    const float* mlpw = (const float*)d_in[map[18]];
    const int*   pci  = (const int*)d_in[map[19]];
    const int*   fci  = (const int*)d_in[map[20]];
    float* out = (float*)d_out;

    void* pv;
    cudaGetSymbolAddress(&pv, g_pf0);  float* pf0 = (float*)pv;
    cudaGetSymbolAddress(&pv, g_pf1);  float* pf1 = (float*)pv;
    cudaGetSymbolAddress(&pv, g_pf2);  float* pf2 = (float*)pv;
    __nv_bfloat16 *w0a, *w0b, *w1a, *w1b, *w2a, *w2b;
    __nv_bfloat16 *x0a, *x0b, *x1a, *x1b, *x2a, *x2b;
    cudaGetSymbolAddress(&pv, g_w0a); w0a = (__nv_bfloat16*)pv;
    cudaGetSymbolAddress(&pv, g_w0b); w0b = (__nv_bfloat16*)pv;
    cudaGetSymbolAddress(&pv, g_w1a); w1a = (__nv_bfloat16*)pv;
    cudaGetSymbolAddress(&pv, g_w1b); w1b = (__nv_bfloat16*)pv;
    cudaGetSymbolAddress(&pv, g_w2a); w2a = (__nv_bfloat16*)pv;
    cudaGetSymbolAddress(&pv, g_w2b); w2b = (__nv_bfloat16*)pv;
    cudaGetSymbolAddress(&pv, g_x0a); x0a = (__nv_bfloat16*)pv;
    cudaGetSymbolAddress(&pv, g_x0b); x0b = (__nv_bfloat16*)pv;
    cudaGetSymbolAddress(&pv, g_x1a); x1a = (__nv_bfloat16*)pv;
    cudaGetSymbolAddress(&pv, g_x1b); x1b = (__nv_bfloat16*)pv;
    cudaGetSymbolAddress(&pv, g_x2a); x2a = (__nv_bfloat16*)pv;
    cudaGetSymbolAddress(&pv, g_x2b); x2b = (__nv_bfloat16*)pv;

    prep_kernel<<<1, 1>>>(pci, fci);

    SplitW SW;
    SW.w[0] = (const float*)d_in[map[3]];
    SW.w[1] = (const float*)d_in[map[8]];
    SW.w[2] = (const float*)d_in[map[13]];
    SW.wa[0] = w0a; SW.wa[1] = w1a; SW.wa[2] = w2a;
    SW.wb[0] = w0b; SW.wb[1] = w1b; SW.wb[2] = w2b;
    wsplit_all<<<dim3(128, 3), 256>>>(SW);

    SplitX SX;
    SX.x[0] = (const float*)d_in[map[0]];
    SX.x[1] = (const float*)d_in[map[1]];
    SX.x[2] = (const float*)d_in[map[2]];
    SX.xa[0] = x0a; SX.xa[1] = x1a; SX.xa[2] = x2a;
    SX.xb[0] = x0b; SX.xb[1] = x1b; SX.xb[2] = x2b;
    xsplit_all<<<dim3(400, 3, NFR), 256>>>(SX);

    ConvTC P;
    P.wa[0] = w0a; P.wa[1] = w1a; P.wa[2] = w2a;
    P.wb[0] = w0b; P.wb[1] = w1b; P.wb[2] = w2b;
    P.xa[0] = x0a; P.xa[1] = x1a; P.xa[2] = x2a;
    P.xb[0] = x0b; P.xb[1] = x1b; P.xb[2] = x2b;
    P.gg[0] = (const float*)d_in[map[4]];  P.gg[1] = (const float*)d_in[map[9]];   P.gg[2] = (const float*)d_in[map[14]];
    P.bb[0] = (const float*)d_in[map[5]];  P.bb[1] = (const float*)d_in[map[10]];  P.bb[2] = (const float*)d_in[map[15]];
    P.mm[0] = (const float*)d_in[map[6]];  P.mm[1] = (const float*)d_in[map[11]];  P.mm[2] = (const float*)d_in[map[16]];
    P.vv[0] = (const float*)d_in[map[7]];  P.vv[1] = (const float*)d_in[map[12]];  P.vv[2] = (const float*)d_in[map[17]];
    P.pf[0] = pf0; P.pf[1] = pf1; P.pf[2] = pf2;

    cudaFuncSetAttribute(conv_bf16_kernel,
                         cudaFuncAttributeMaxDynamicSharedMemorySize, 3 * 32768);
    conv_bf16_kernel<<<dim3(92, 1, NFR), 256, 3 * 32768>>>(P);

    size_t sm0 = (size_t)(112 * 112 + 2 * 8 * NS) * sizeof(float);
    size_t sm1 = (size_t)( 56 *  56 + 2 * 8 * NS) * sizeof(float);
    size_t sm2 = (size_t)( 28 *  28 + 2 * 4 * NS) * sizeof(float);
    cudaFuncSetAttribute((const void*)corr2_kernel<128, 80, 80, 4, 7, 256, 0>,
                         cudaFuncAttributeMaxDynamicSharedMemorySize, 65536);

    corr2_kernel<128, 80, 80, 4, 7, 256,  0><<<dim3(128, BB), 256, sm0>>>(pf0, mlpw, out, 0);
    corr2_kernel<256, 40, 40, 2, 2, 256, 20><<<dim3(256, BB), 256, sm1>>>(pf1, mlpw, out, 1024);
    corr2_kernel<512, 20, 20, 1, 1, 128, 12><<<dim3(512, BB), 128, sm2>>>(pf2, mlpw, out, 3072);
}

// round 11
// speedup vs baseline: 1.0502x; 1.0036x over previous
#include <cuda_runtime.h>
#include <cuda_bf16.h>
#include <math.h>
#include <stdint.h>

#define BB    4
#define TPP   4
#define TFF   2
#define NPAIR (BB*TFF)
#define RAD   4
#define NS    81
#define NFR   (BB*TPP)

// ---------------- scratch ---------------------------------------------------------
__device__ int   g_idx[NPAIR];
__device__ int   g_needed[NFR];
__device__ float g_pf0[(size_t)NFR * 128 * 6400];
__device__ float g_pf1[(size_t)NFR * 256 * 1600];
__device__ float g_pf2[(size_t)NFR * 512 * 400];
__device__ __nv_bfloat16 g_w0a[128*128],  g_w0b[128*128];
__device__ __nv_bfloat16 g_w1a[256*256],  g_w1b[256*256];
__device__ __nv_bfloat16 g_w2a[512*512],  g_w2b[512*512];
__device__ __nv_bfloat16 g_x0a[(size_t)NFR*128*6400], g_x0b[(size_t)NFR*128*6400];
__device__ __nv_bfloat16 g_x1a[(size_t)NFR*256*1664], g_x1b[(size_t)NFR*256*1664];
__device__ __nv_bfloat16 g_x2a[(size_t)NFR*512*512],  g_x2b[(size_t)NFR*512*512];

// ---------------- prep ------------------------------------------------------------
__global__ void prep_kernel(const int* __restrict__ pci, const int* __restrict__ fci)
{
    if (threadIdx.x != 0 || blockIdx.x != 0) return;
    for (int n = 0; n < NFR; n++) g_needed[n] = 0;
    for (int i = 0; i < BB; i++) {
        int p_pos = TPP - 2;
        for (int j = 0; j < TFF; j++) {
            int f_i = fci[i * TFF + j];
            while (p_pos >= 0) {
                if (p_pos == 0 || f_i < -pci[i * TPP + p_pos - 1]) {
                    int id = p_pos + i * TPP;
                    g_idx[i * TFF + j] = id;
                    g_needed[id] = 1;
                    break;
                }
                p_pos--;
            }
        }
        g_needed[i * TPP + (TPP - 1)] = 1;
    }
}

// ---------------- fused split kernels ---------------------------------------------
union BV8 { __nv_bfloat16 h[8]; uint4 u; };

__device__ __forceinline__ void split8(const float* v, uint4* ua, uint4* ub)
{
    BV8 a, b;
#pragma unroll
    for (int j = 0; j < 8; j++) {
        __nv_bfloat16 h = __float2bfloat16(v[j]);
        a.h[j] = h;
        b.h[j] = __float2bfloat16(v[j] - __bfloat162float(h));
    }
    *ua = a.u; *ub = b.u;
}

struct SplitW {
    const float* w[3];
    __nv_bfloat16 *wa[3], *wb[3];
};

__global__ void wsplit_all(SplitW S)
{
    int lvl = blockIdx.y;
    int nE  = (128 << lvl) * (128 << lvl);
    int i   = (blockIdx.x * 256 + threadIdx.x) * 8;
    if (i < nE) {
        float v[8];
        *(float4*)&v[0] = *(const float4*)(S.w[lvl] + i);
        *(float4*)&v[4] = *(const float4*)(S.w[lvl] + i + 4);
        split8(v, (uint4*)(S.wa[lvl] + i), (uint4*)(S.wb[lvl] + i));
    }
}

struct SplitX {
    const float* x[3];
    __nv_bfloat16 *xa[3], *xb[3];
};

__global__ void xsplit_all(SplitX S)
{
    int n = blockIdx.z;
    if (!g_needed[n]) return;
    int lvl = blockIdx.y;
    const int C     = 128 << lvl;
    const int HW    = 6400 >> (2 * lvl);
    const int HWpad = (lvl == 0) ? 6400 : (lvl == 1 ? 1664 : 512);
    int tot = C * HWpad;
    int i = (blockIdx.x * 256 + threadIdx.x) * 8;
    if (i >= tot) return;
    int c = i / HWpad, p = i - c * HWpad;
    float v[8];
    if (p + 8 <= HW) {
        const float* s = S.x[lvl] + (size_t)n * C * HW + (size_t)c * HW + p;
        *(float4*)&v[0] = *(const float4*)s;
        *(float4*)&v[4] = *(const float4*)(s + 4);
    } else {
#pragma unroll
        for (int j = 0; j < 8; j++) v[j] = 0.f;
    }
    size_t o = (size_t)n * tot + i;
    split8(v, (uint4*)(S.xa[lvl] + o), (uint4*)(S.xb[lvl] + o));
}

// ---------------- mma.sync bf16 helpers -------------------------------------------
__device__ __forceinline__ uint32_t smem_u32(const void* p)
{
    uint32_t a;
    asm("{ .reg .u64 t; cvta.to.shared.u64 t, %1; cvt.u32.u64 %0, t; }" : "=r"(a) : "l"(p));
    return a;
}

__device__ __forceinline__ void ldm_x4(uint32_t* r, uint32_t addr)
{
    asm volatile("ldmatrix.sync.aligned.m8n8.x4.shared.b16 {%0,%1,%2,%3}, [%4];"
                 : "=r"(r[0]), "=r"(r[1]), "=r"(r[2]), "=r"(r[3]) : "r"(addr));
}

__device__ __forceinline__ void ldm_x4t(uint32_t* r, uint32_t addr)
{
    asm volatile("ldmatrix.sync.aligned.m8n8.x4.trans.shared.b16 {%0,%1,%2,%3}, [%4];"
                 : "=r"(r[0]), "=r"(r[1]), "=r"(r[2]), "=r"(r[3]) : "r"(addr));
}

__device__ __forceinline__ void mma16(float* c, const uint32_t* a, const uint32_t* b)
{
    asm volatile(
        "mma.sync.aligned.m16n8k16.row.col.f32.bf16.bf16.f32 "
        "{%0,%1,%2,%3}, {%4,%5,%6,%7}, {%8,%9}, {%0,%1,%2,%3};"
        : "+f"(c[0]), "+f"(c[1]), "+f"(c[2]), "+f"(c[3])
        : "r"(a[0]), "r"(a[1]), "r"(a[2]), "r"(a[3]), "r"(b[0]), "r"(b[1]));
}

__device__ __forceinline__ void cpa16(uint32_t dst, const void* src)
{
    asm volatile("cp.async.cg.shared.global [%0], [%1], 16;" :: "r"(dst), "l"(src));
}

__device__ __forceinline__ float silu(float y) { return y / (1.0f + expf(-y)); }

// ---------------- conv: bf16 3-term mma.sync, 3-stage pipeline --------------------
// term-major MMA ordering: consecutive MMAs hit different accumulators (no RAW chain)
struct ConvTC {
    const __nv_bfloat16 *wa[3], *wb[3], *xa[3], *xb[3];
    const float *gg[3], *bb[3], *mm[3], *vv[3];
    float *pf[3];
};

__global__ void __launch_bounds__(256, 2) conv_bf16_kernel(ConvTC P)
{
    int n = blockIdx.z;
    if (!g_needed[n]) return;

    int bx = blockIdx.x, lvl, p0, d0;
    if (bx < 50)      { lvl = 0; p0 = bx * 128; d0 = 0; }
    else if (bx < 76) { int r = bx - 50; lvl = 1; p0 = (r % 13) * 128; d0 = (r / 13) * 128; }
    else              { int r = bx - 76; lvl = 2; p0 = (r & 3) * 128;  d0 = (r >> 2) * 128; }
    const int C     = 128 << lvl;
    const int HW    = 6400 >> (2 * lvl);
    const int HWpad = (lvl == 0) ? 6400 : (lvl == 1 ? 1664 : 512);
    const int NC    = C >> 5;

    extern __shared__ uint32_t dsm[];
    const int tid  = threadIdx.x;
    const int lane = tid & 31;
    const int wid  = tid >> 5;
    const int m_off = (wid & 1) * 64;
    const int n_off = (wid >> 1) * 32;
    const int g  = lane >> 2;
    const int tg = lane & 3;
    const uint32_t smb = smem_u32(dsm);

    const __nv_bfloat16* wA1 = P.wa[lvl] + (size_t)d0 * C;
    const __nv_bfloat16* wA2 = P.wb[lvl] + (size_t)d0 * C;
    const __nv_bfloat16* xB1 = P.xa[lvl] + (size_t)n * C * HWpad + p0;
    const __nv_bfloat16* xB2 = P.xb[lvl] + (size_t)n * C * HWpad + p0;

    float acc[4][4][4];
#pragma unroll
    for (int mi = 0; mi < 4; mi++)
#pragma unroll
        for (int ni = 0; ni < 4; ni++)
#pragma unroll
            for (int r = 0; r < 4; r++) acc[mi][ni][r] = 0.f;

    const int ar0 = tid >> 2,          acb0 = tid & 3;
    const int ar1 = (tid + 256) >> 2,  acb1 = (tid + 256) & 3;
    const int br0 = tid >> 4,          bnb0 = tid & 15;
    const int br1 = (tid + 256) >> 4,  bnb1 = (tid + 256) & 15;
    const uint32_t adof0 = ar0 * 64 + ((acb0 ^ ((ar0 >> 1) & 3)) << 4);
    const uint32_t adof1 = ar1 * 64 + ((acb1 ^ ((ar1 >> 1) & 3)) << 4);
    const uint32_t bdof0 = br0 * 256 + ((bnb0 ^ (br0 & 7)) << 4);
    const uint32_t bdof1 = br1 * 256 + ((bnb1 ^ (br1 & 7)) << 4);

#define STAGE(BUF, KC)                                                              \
    do {                                                                            \
        int k0_ = (KC) * 32;                                                        \
        uint32_t bbuf = smb + (BUF) * 32768;                                        \
        cpa16(bbuf + adof0,         wA1 + (size_t)ar0 * C + k0_ + acb0 * 8);        \
        cpa16(bbuf + adof1,         wA1 + (size_t)ar1 * C + k0_ + acb1 * 8);        \
        cpa16(bbuf + 8192 + adof0,  wA2 + (size_t)ar0 * C + k0_ + acb0 * 8);        \
        cpa16(bbuf + 8192 + adof1,  wA2 + (size_t)ar1 * C + k0_ + acb1 * 8);        \
        cpa16(bbuf + 16384 + bdof0, xB1 + (size_t)(k0_ + br0) * HWpad + bnb0 * 8);  \
        cpa16(bbuf + 16384 + bdof1, xB1 + (size_t)(k0_ + br1) * HWpad + bnb1 * 8);  \
        cpa16(bbuf + 24576 + bdof0, xB2 + (size_t)(k0_ + br0) * HWpad + bnb0 * 8);  \
        cpa16(bbuf + 24576 + bdof1, xB2 + (size_t)(k0_ + br1) * HWpad + bnb1 * 8);  \
        asm volatile("cp.async.commit_group;");                                     \
    } while (0)

    STAGE(0, 0);
    STAGE(1, 1);

    int cur = 0;
    const int ks_xor = wid & 1;
    for (int kc = 0; kc < NC; kc++) {
        if (kc + 1 < NC) {
            asm volatile("cp.async.wait_group 1;");
        } else {
            asm volatile("cp.async.wait_group 0;");
        }
        __syncthreads();

        if (kc + 2 < NC) {
            int nb = cur + 2;
            if (nb >= 3) nb -= 3;
            STAGE(nb, kc + 2);
        }

        uint32_t base = smb + cur * 32768;
#pragma unroll
        for (int ksi = 0; ksi < 2; ksi++) {
            int ks = ksi ^ ks_xor;
            uint32_t bhf[2][4], blf[2][4];
            int brow = ks * 16 + (lane & 15);
            int nbb  = (n_off >> 3) + (lane >> 4);
#pragma unroll
            for (int nip = 0; nip < 2; nip++) {
                uint32_t boff = brow * 256 + (((nbb + nip * 2) ^ (brow & 7)) << 4);
                ldm_x4t(bhf[nip], base + 16384 + boff);
                ldm_x4t(blf[nip], base + 24576 + boff);
            }
#pragma unroll
            for (int mi = 0; mi < 4; mi++) {
                int arow = m_off + mi * 16 + (lane & 15);
                int cb   = ks * 2 + (lane >> 4);
                uint32_t aoff = arow * 64 + ((cb ^ ((arow >> 1) & 3)) << 4);
                uint32_t ah[4], al[4];
                ldm_x4(ah, base + aoff);
                ldm_x4(al, base + 8192 + aoff);
                // term-major: 4 independent accumulators between revisits
#pragma unroll
                for (int ni = 0; ni < 4; ni++)
                    mma16(acc[mi][ni], ah, &bhf[ni >> 1][(ni & 1) * 2]);
#pragma unroll
                for (int ni = 0; ni < 4; ni++)
                    mma16(acc[mi][ni], ah, &blf[ni >> 1][(ni & 1) * 2]);
#pragma unroll
                for (int ni = 0; ni < 4; ni++)
                    mma16(acc[mi][ni], al, &bhf[ni >> 1][(ni & 1) * 2]);
            }
        }
        cur = (cur + 1 == 3) ? 0 : cur + 1;
    }

    const float* gg  = P.gg[lvl];
    const float* bbp = P.bb[lvl];
    const float* mm  = P.mm[lvl];
    const float* vv  = P.vv[lvl];
    float*       pf  = P.pf[lvl];
#pragma unroll
    for (int mi = 0; mi < 4; mi++) {
        int r0 = d0 + m_off + mi * 16 + g;
        int r1 = r0 + 8;
        float sc0 = gg[r0] * (1.0f / sqrtf(vv[r0] + 1e-5f));
        float bi0 = bbp[r0] - mm[r0] * sc0;
        float sc1 = gg[r1] * (1.0f / sqrtf(vv[r1] + 1e-5f));
        float bi1 = bbp[r1] - mm[r1] * sc1;
        float* op0 = pf + ((size_t)n * C + r0) * HW;
        float* op1 = pf + ((size_t)n * C + r1) * HW;
#pragma unroll
        for (int ni = 0; ni < 4; ni++) {
            int p = p0 + n_off + ni * 8 + 2 * tg;
            if (p < HW) {
                *(float2*)(op0 + p) = make_float2(silu(acc[mi][ni][0] * sc0 + bi0),
                                                  silu(acc[mi][ni][1] * sc0 + bi0));
                *(float2*)(op1 + p) = make_float2(silu(acc[mi][ni][2] * sc1 + bi1),
                                                  silu(acc[mi][ni][3] * sc1 + bi1));
            }
        }
    }
}

// ---------------- corr (R8 known-good) --------------------------------------------
template<int C, int H, int W, int STEP, int NG, int NT, int WINL>
__global__ void __launch_bounds__(NT) corr2_kernel(
    const float* __restrict__ pf, const float* __restrict__ mlpw,
    float* __restrict__ out, int out_off)
{
    constexpr int PAD = RAD * STEP;
    constexpr int W2  = W + 2 * PAD;
    constexpr int H2  = H + 2 * PAD;
    constexpr int HW  = H * W;
    constexpr int NW  = NT / 32;

    extern __shared__ float sm[];
    float* f1p  = sm;
    float* wred = sm + H2 * W2;

    const int c    = blockIdx.x;
    const int b    = blockIdx.y;
    const int n1   = b * TPP + (TPP - 1);
    const int n2a  = g_idx[b * TFF + 0];
    const int n2b  = g_idx[b * TFF + 1];
    const int tid  = threadIdx.x;
    const int wid  = tid >> 5;
    const int lane = tid & 31;

    const float* f1g = pf + ((size_t)n1  * C + c) * HW;
    const float* f2a = pf + ((size_t)n2a * C + c) * HW;
    const float* f2b = pf + ((size_t)n2b * C + c) * HW;

    for (int q = tid; q < H2 * W2; q += NT) {
        int hh = q / W2 - PAD;
        int ww = q % W2 - PAD;
        float v = 0.f;
        if ((unsigned)hh < (unsigned)H && (unsigned)ww < (unsigned)W)
            v = f1g[hh * W + ww];
        f1p[q] = v;
    }

    float fra[NG][4], frb[NG][4];
    int   basek[NG];
#pragma unroll
    for (int gi = 0; gi < NG; gi++) {
        int p = (tid + NT * gi) * 4;
        if (p < HW) {
            float4 va = *(const float4*)(f2a + p);
            float4 vb = *(const float4*)(f2b + p);
            fra[gi][0] = va.x; fra[gi][1] = va.y; fra[gi][2] = va.z; fra[gi][3] = va.w;
            frb[gi][0] = vb.x; frb[gi][1] = vb.y; frb[gi][2] = vb.z; frb[gi][3] = vb.w;
            basek[gi] = (p / W + PAD) * W2 + (p % W) + PAD;
        } else {
#pragma unroll
            for (int v = 0; v < 4; v++) { fra[gi][v] = 0.f; frb[gi][v] = 0.f; }
            basek[gi] = PAD * W2 + PAD;
        }
    }
    __syncthreads();

    if (WINL == 0) {
        for (int oy = 0; oy < 9; oy++) {
            int ro[NG];
            int dyo = (oy - RAD) * STEP * W2;
#pragma unroll
            for (int gi = 0; gi < NG; gi++) ro[gi] = basek[gi] + dyo;
#pragma unroll
            for (int ox = 0; ox < 9; ox++) {
                const int dxo = (ox - RAD) * STEP;
                float a0 = 0.f, a1 = 0.f, b0 = 0.f, b1 = 0.f;
#pragma unroll
                for (int gi = 0; gi < NG; gi++) {
                    float4 fv = *(const float4*)&f1p[ro[gi] + dxo];
                    a0 = fmaf(fv.x, fra[gi][0], a0);
                    a1 = fmaf(fv.y, fra[gi][1], a1);
                    a0 = fmaf(fv.z, fra[gi][2], a0);
                    a1 = fmaf(fv.w, fra[gi][3], a1);
                    b0 = fmaf(fv.x, frb[gi][0], b0);
                    b1 = fmaf(fv.y, frb[gi][1], b1);
                    b0 = fmaf(fv.z, frb[gi][2], b0);
                    b1 = fmaf(fv.w, frb[gi][3], b1);
                }
                float va = a0 + a1, vb = b0 + b1;
#pragma unroll
                for (int o = 16; o; o >>= 1) {
                    va += __shfl_xor_sync(0xffffffffu, va, o);
                    vb += __shfl_xor_sync(0xffffffffu, vb, o);
                }
                if (lane == 0) {
                    wred[(0 * NW + wid) * NS + oy * 9 + ox] = va;
                    wred[(1 * NW + wid) * NS + oy * 9 + ox] = vb;
                }
            }
        }
    } else {
        for (int oy = 0; oy < 9; oy++) {
            int dyo = (oy - RAD) * STEP * W2;
            float aA[9], aB[9];
#pragma unroll
            for (int ox = 0; ox < 9; ox++) { aA[ox] = 0.f; aB[ox] = 0.f; }
#pragma unroll
            for (int gi = 0; gi < NG; gi++) {
                const float* wp = &f1p[basek[gi] + dyo - 4 * STEP];
                float win[WINL > 0 ? WINL : 1];
#pragma unroll
                for (int t = 0; t < WINL / 4; t++) {
                    float4 v = *(const float4*)(wp + 4 * t);
                    win[4 * t] = v.x; win[4 * t + 1] = v.y;
                    win[4 * t + 2] = v.z; win[4 * t + 3] = v.w;
                }
#pragma unroll
                for (int ox = 0; ox < 9; ox++) {
#pragma unroll
                    for (int j = 0; j < 4; j++) {
                        aA[ox] = fmaf(win[STEP * ox + j], fra[gi][j], aA[ox]);
                        aB[ox] = fmaf(win[STEP * ox + j], frb[gi][j], aB[ox]);
                    }
                }
            }
#pragma unroll
            for (int ox = 0; ox < 9; ox++) {
                float va = aA[ox], vb = aB[ox];
#pragma unroll
                for (int o = 16; o; o >>= 1) {
                    va += __shfl_xor_sync(0xffffffffu, va, o);
                    vb += __shfl_xor_sync(0xffffffffu, vb, o);
                }
                if (lane == 0) {
                    wred[(0 * NW + wid) * NS + oy * 9 + ox] = va;
                    wred[(1 * NW + wid) * NS + oy * 9 + ox] = vb;
                }
            }
        }
    }
    __syncthreads();

    if (tid < 64) {
        int q = tid >> 5, l = tid & 31;
        const float* wr = wred + q * NW * NS;
        float v0, v1 = -1e30f, v2 = -1e30f;
        {
            float s0 = 0.f, s1 = 0.f, s2 = 0.f;
#pragma unroll
            for (int w = 0; w < NW; w++) {
                s0 += wr[w * NS + l];
                if (l + 32 < NS) s1 += wr[w * NS + l + 32];
                if (l + 64 < NS) s2 += wr[w * NS + l + 64];
            }
            v0 = s0;
            if (l + 32 < NS) v1 = s1;
            if (l + 64 < NS) v2 = s2;
        }
        float mx = fmaxf(v0, fmaxf(v1, v2));
#pragma unroll
        for (int o = 16; o; o >>= 1)
            mx = fmaxf(mx, __shfl_xor_sync(0xffffffffu, mx, o));
        float e0 = expf(v0 - mx);
        float e1 = (l + 32 < NS) ? expf(v1 - mx) : 0.f;
        float e2 = (l + 64 < NS) ? expf(v2 - mx) : 0.f;
        float w0 = mlpw[l];
        float w1 = (l + 32 < NS) ? mlpw[l + 32] : 0.f;
        float w2 = (l + 64 < NS) ? mlpw[l + 64] : 0.f;
        float ssum = e0 + e1 + e2;
        float dot  = e0 * w0 + e1 * w1 + e2 * w2;
#pragma unroll
        for (int o = 16; o; o >>= 1) {
            ssum += __shfl_xor_sync(0xffffffffu, ssum, o);
            dot  += __shfl_xor_sync(0xffffffffu, dot,  o);
        }
        if (l == 0)
            out[out_off + (b * TFF + q) * C + c] = dot / ssum;
    }
}

// ---------------- launch ----------------------------------------------------------
extern "C" void kernel_launch(void* const* d_in, const int* in_sizes, int n_in,
                              void* d_out, int out_size)
{
    int map_sig [21] = {0,1,2, 3,4,5,6,7, 8,9,10,11,12, 13,14,15,16,17, 18,19,20};
    int map_dict[21] = {0,6,12, 1,2,3,4,5, 7,8,9,10,11, 13,14,15,16,17, 18,19,20};
    const int* map = (in_sizes[1] == 16384) ? map_dict : map_sig;

    const float* mlpw = (const float*)d_in[map[18]];
    const int*   pci  = (const int*)d_in[map[19]];
    const int*   fci  = (const int*)d_in[map[20]];
    float* out = (float*)d_out;

    void* pv;
    cudaGetSymbolAddress(&pv, g_pf0);  float* pf0 = (float*)pv;
    cudaGetSymbolAddress(&pv, g_pf1);  float* pf1 = (float*)pv;
    cudaGetSymbolAddress(&pv, g_pf2);  float* pf2 = (float*)pv;
    __nv_bfloat16 *w0a, *w0b, *w1a, *w1b, *w2a, *w2b;
    __nv_bfloat16 *x0a, *x0b, *x1a, *x1b, *x2a, *x2b;
    cudaGetSymbolAddress(&pv, g_w0a); w0a = (__nv_bfloat16*)pv;
    cudaGetSymbolAddress(&pv, g_w0b); w0b = (__nv_bfloat16*)pv;
    cudaGetSymbolAddress(&pv, g_w1a); w1a = (__nv_bfloat16*)pv;
    cudaGetSymbolAddress(&pv, g_w1b); w1b = (__nv_bfloat16*)pv;
    cudaGetSymbolAddress(&pv, g_w2a); w2a = (__nv_bfloat16*)pv;
    cudaGetSymbolAddress(&pv, g_w2b); w2b = (__nv_bfloat16*)pv;
    cudaGetSymbolAddress(&pv, g_x0a); x0a = (__nv_bfloat16*)pv;
    cudaGetSymbolAddress(&pv, g_x0b); x0b = (__nv_bfloat16*)pv;
    cudaGetSymbolAddress(&pv, g_x1a); x1a = (__nv_bfloat16*)pv;
    cudaGetSymbolAddress(&pv, g_x1b); x1b = (__nv_bfloat16*)pv;
    cudaGetSymbolAddress(&pv, g_x2a); x2a = (__nv_bfloat16*)pv;
    cudaGetSymbolAddress(&pv, g_x2b); x2b = (__nv_bfloat16*)pv;

    prep_kernel<<<1, 1>>>(pci, fci);

    SplitW SW;
    SW.w[0] = (const float*)d_in[map[3]];
    SW.w[1] = (const float*)d_in[map[8]];
    SW.w[2] = (const float*)d_in[map[13]];
    SW.wa[0] = w0a; SW.wa[1] = w1a; SW.wa[2] = w2a;
    SW.wb[0] = w0b; SW.wb[1] = w1b; SW.wb[2] = w2b;
    wsplit_all<<<dim3(128, 3), 256>>>(SW);

    SplitX SX;
    SX.x[0] = (const float*)d_in[map[0]];
    SX.x[1] = (const float*)d_in[map[1]];
    SX.x[2] = (const float*)d_in[map[2]];
    SX.xa[0] = x0a; SX.xa[1] = x1a; SX.xa[2] = x2a;
    SX.xb[0] = x0b; SX.xb[1] = x1b; SX.xb[2] = x2b;
    xsplit_all<<<dim3(400, 3, NFR), 256>>>(SX);

    ConvTC P;
    P.wa[0] = w0a; P.wa[1] = w1a; P.wa[2] = w2a;
    P.wb[0] = w0b; P.wb[1] = w1b; P.wb[2] = w2b;
    P.xa[0] = x0a; P.xa[1] = x1a; P.xa[2] = x2a;
    P.xb[0] = x0b; P.xb[1] = x1b; P.xb[2] = x2b;
    P.gg[0] = (const float*)d_in[map[4]];  P.gg[1] = (const float*)d_in[map[9]];   P.gg[2] = (const float*)d_in[map[14]];
    P.bb[0] = (const float*)d_in[map[5]];  P.bb[1] = (const float*)d_in[map[10]];  P.bb[2] = (const float*)d_in[map[15]];
    P.mm[0] = (const float*)d_in[map[6]];  P.mm[1] = (const float*)d_in[map[11]];  P.mm[2] = (const float*)d_in[map[16]];
    P.vv[0] = (const float*)d_in[map[7]];  P.vv[1] = (const float*)d_in[map[12]];  P.vv[2] = (const float*)d_in[map[17]];
    P.pf[0] = pf0; P.pf[1] = pf1; P.pf[2] = pf2;

    cudaFuncSetAttribute(conv_bf16_kernel,
                         cudaFuncAttributeMaxDynamicSharedMemorySize, 3 * 32768);
    conv_bf16_kernel<<<dim3(92, 1, NFR), 256, 3 * 32768>>>(P);

    size_t sm0 = (size_t)(112 * 112 + 2 * 8 * NS) * sizeof(float);
    size_t sm1 = (size_t)( 56 *  56 + 2 * 8 * NS) * sizeof(float);
    size_t sm2 = (size_t)( 28 *  28 + 2 * 4 * NS) * sizeof(float);
    cudaFuncSetAttribute((const void*)corr2_kernel<128, 80, 80, 4, 7, 256, 0>,
                         cudaFuncAttributeMaxDynamicSharedMemorySize, 65536);

    corr2_kernel<128, 80, 80, 4, 7, 256,  0><<<dim3(128, BB), 256, sm0>>>(pf0, mlpw, out, 0);
    corr2_kernel<256, 40, 40, 2, 2, 256, 20><<<dim3(256, BB), 256, sm1>>>(pf1, mlpw, out, 1024);
    corr2_kernel<512, 20, 20, 1, 1, 128, 12><<<dim3(512, BB), 128, sm2>>>(pf2, mlpw, out, 3072);
}

// round 12
// speedup vs baseline: 1.1567x; 1.1014x over previous
#include <cuda_runtime.h>
#include <cuda_bf16.h>
#include <math.h>
#include <stdint.h>

#define BB    4
#define TPP   4
#define TFF   2
#define NPAIR (BB*TFF)
#define RAD   4
#define NS    81
#define NFR   (BB*TPP)

// ---------------- scratch ---------------------------------------------------------
__device__ int   g_idx[NPAIR];
__device__ int   g_needed[NFR];
__device__ float g_pf0[(size_t)NFR * 128 * 6400];
__device__ float g_pf1[(size_t)NFR * 256 * 1600];
__device__ float g_pf2[(size_t)NFR * 512 * 400];
__device__ __nv_bfloat16 g_w0a[128*128],  g_w0b[128*128];
__device__ __nv_bfloat16 g_w1a[256*256],  g_w1b[256*256];
__device__ __nv_bfloat16 g_w2a[512*512],  g_w2b[512*512];

// ---------------- prep ------------------------------------------------------------
__global__ void prep_kernel(const int* __restrict__ pci, const int* __restrict__ fci)
{
    if (threadIdx.x != 0 || blockIdx.x != 0) return;
    for (int n = 0; n < NFR; n++) g_needed[n] = 0;
    for (int i = 0; i < BB; i++) {
        int p_pos = TPP - 2;
        for (int j = 0; j < TFF; j++) {
            int f_i = fci[i * TFF + j];
            while (p_pos >= 0) {
                if (p_pos == 0 || f_i < -pci[i * TPP + p_pos - 1]) {
                    int id = p_pos + i * TPP;
                    g_idx[i * TFF + j] = id;
                    g_needed[id] = 1;
                    break;
                }
                p_pos--;
            }
        }
        g_needed[i * TPP + (TPP - 1)] = 1;
    }
}

// ---------------- W split (fused over levels) --------------------------------------
union BV8 { __nv_bfloat16 h[8]; uint4 u; };

__device__ __forceinline__ void split8(const float* v, uint4* ua, uint4* ub)
{
    BV8 a, b;
#pragma unroll
    for (int j = 0; j < 8; j++) {
        __nv_bfloat16 h = __float2bfloat16(v[j]);
        a.h[j] = h;
        b.h[j] = __float2bfloat16(v[j] - __bfloat162float(h));
    }
    *ua = a.u; *ub = b.u;
}

struct SplitW {
    const float* w[3];
    __nv_bfloat16 *wa[3], *wb[3];
};

__global__ void wsplit_all(SplitW S)
{
    int lvl = blockIdx.y;
    int nE  = (128 << lvl) * (128 << lvl);
    int i   = (blockIdx.x * 256 + threadIdx.x) * 8;
    if (i < nE) {
        float v[8];
        *(float4*)&v[0] = *(const float4*)(S.w[lvl] + i);
        *(float4*)&v[4] = *(const float4*)(S.w[lvl] + i + 4);
        split8(v, (uint4*)(S.wa[lvl] + i), (uint4*)(S.wb[lvl] + i));
    }
}

// ---------------- mma.sync bf16 helpers -------------------------------------------
__device__ __forceinline__ uint32_t smem_u32(const void* p)
{
    uint32_t a;
    asm("{ .reg .u64 t; cvta.to.shared.u64 t, %1; cvt.u32.u64 %0, t; }" : "=r"(a) : "l"(p));
    return a;
}

__device__ __forceinline__ void ldm_x4(uint32_t* r, uint32_t addr)
{
    asm volatile("ldmatrix.sync.aligned.m8n8.x4.shared.b16 {%0,%1,%2,%3}, [%4];"
                 : "=r"(r[0]), "=r"(r[1]), "=r"(r[2]), "=r"(r[3]) : "r"(addr));
}

__device__ __forceinline__ void ldm_x4t(uint32_t* r, uint32_t addr)
{
    asm volatile("ldmatrix.sync.aligned.m8n8.x4.trans.shared.b16 {%0,%1,%2,%3}, [%4];"
                 : "=r"(r[0]), "=r"(r[1]), "=r"(r[2]), "=r"(r[3]) : "r"(addr));
}

__device__ __forceinline__ void mma16(float* c, const uint32_t* a, const uint32_t* b)
{
    asm volatile(
        "mma.sync.aligned.m16n8k16.row.col.f32.bf16.bf16.f32 "
        "{%0,%1,%2,%3}, {%4,%5,%6,%7}, {%8,%9}, {%0,%1,%2,%3};"
        : "+f"(c[0]), "+f"(c[1]), "+f"(c[2]), "+f"(c[3])
        : "r"(a[0]), "r"(a[1]), "r"(a[2]), "r"(a[3]), "r"(b[0]), "r"(b[1]));
}

__device__ __forceinline__ void cpa16(uint32_t dst, const void* src)
{
    asm volatile("cp.async.cg.shared.global [%0], [%1], 16;" :: "r"(dst), "l"(src));
}

__device__ __forceinline__ float silu(float y) { return y / (1.0f + expf(-y)); }

// ---------------- conv: bf16 3-term mma.sync, fp32 X converted in-kernel ----------
// buffer (48 KB): Ah@0 [128][32]b16, Al@8192, Bh@16384 [32][128]b16, Bl@24576,
//                 Xf@32768 [32][128]fp32.  2 buffers = 96 KB dyn smem.
#define BUFSZ 49152

struct ConvTC {
    const __nv_bfloat16 *wa[3], *wb[3];
    const float *x[3];
    const float *gg[3], *bb[3], *mm[3], *vv[3];
    float *pf[3];
};

__global__ void __launch_bounds__(256, 2) conv_bf16_kernel(ConvTC P)
{
    int n = blockIdx.z;
    if (!g_needed[n]) return;

    int bx = blockIdx.x, lvl, p0, d0;
    if (bx < 50)      { lvl = 0; p0 = bx * 128; d0 = 0; }
    else if (bx < 76) { int r = bx - 50; lvl = 1; p0 = (r % 13) * 128; d0 = (r / 13) * 128; }
    else              { int r = bx - 76; lvl = 2; p0 = (r & 3) * 128;  d0 = (r >> 2) * 128; }
    const int C  = 128 << lvl;
    const int HW = 6400 >> (2 * lvl);
    const int NC = C >> 5;

    extern __shared__ uint32_t dsm[];
    char* smp = (char*)dsm;
    const int tid  = threadIdx.x;
    const int lane = tid & 31;
    const int wid  = tid >> 5;
    const int m_off = (wid & 1) * 64;
    const int n_off = (wid >> 1) * 32;
    const int g  = lane >> 2;
    const int tg = lane & 3;
    const uint32_t smb = smem_u32(dsm);

    const __nv_bfloat16* wA1 = P.wa[lvl] + (size_t)d0 * C;
    const __nv_bfloat16* wA2 = P.wb[lvl] + (size_t)d0 * C;
    const float*         xf  = P.x[lvl] + (size_t)n * C * HW;

    float acc[4][4][4];
#pragma unroll
    for (int mi = 0; mi < 4; mi++)
#pragma unroll
        for (int ni = 0; ni < 4; ni++)
#pragma unroll
            for (int r = 0; r < 4; r++) acc[mi][ni][r] = 0.f;

    // A staging slots
    const int ar0 = tid >> 2,          acb0 = tid & 3;
    const int ar1 = (tid + 256) >> 2,  acb1 = (tid + 256) & 3;
    const uint32_t adof0 = ar0 * 64 + ((acb0 ^ ((ar0 >> 1) & 3)) << 4);
    const uint32_t adof1 = ar1 * 64 + ((acb1 ^ ((ar1 >> 1) & 3)) << 4);

    // B convert mapping: thread -> row r2, 16-float column group cg
    const int r2  = tid >> 3;
    const int cg  = (tid & 7) * 16;
    const int nb0 = (tid & 7) * 2;
    const uint32_t bo0 = r2 * 256 + ((nb0 ^ (r2 & 7)) << 4);
    const uint32_t bo1 = r2 * 256 + (((nb0 + 1) ^ (r2 & 7)) << 4);

#define STAGE(BUF, KC)                                                              \
    do {                                                                            \
        int k0_ = (KC) * 32;                                                        \
        uint32_t bbuf = smb + (BUF) * BUFSZ;                                        \
        cpa16(bbuf + adof0,        wA1 + (size_t)ar0 * C + k0_ + acb0 * 8);         \
        cpa16(bbuf + adof1,        wA1 + (size_t)ar1 * C + k0_ + acb1 * 8);         \
        cpa16(bbuf + 8192 + adof0, wA2 + (size_t)ar0 * C + k0_ + acb0 * 8);         \
        cpa16(bbuf + 8192 + adof1, wA2 + (size_t)ar1 * C + k0_ + acb1 * 8);         \
        _Pragma("unroll")                                                           \
        for (int t = 0; t < 4; t++) {                                               \
            int slot = tid + t * 256;                                               \
            int rr   = slot >> 5;                                                   \
            int c4   = (slot & 31) * 4;                                             \
            if (p0 + c4 < HW)                                                       \
                cpa16(bbuf + 32768 + slot * 16,                                     \
                      xf + (size_t)(k0_ + rr) * HW + p0 + c4);                      \
            else                                                                    \
                *(uint4*)(smp + (BUF) * BUFSZ + 32768 + slot * 16) =                \
                    make_uint4(0, 0, 0, 0);                                         \
        }                                                                           \
        asm volatile("cp.async.commit_group;");                                     \
    } while (0)

    STAGE(0, 0);

    int cur = 0;
    for (int kc = 0; kc < NC; kc++) {
        asm volatile("cp.async.wait_group 0;");
        __syncthreads();   // staged cur visible; all MMA reads of other buffer done

        // ---- convert B: Xf(cur) fp32 -> Bh/Bl(cur) bf16 swizzled ----
        {
            char* bufp = smp + cur * BUFSZ;
            const float* xs = (const float*)(bufp + 32768) + r2 * 128 + cg;
            float v[16];
            *(float4*)&v[0]  = *(const float4*)(xs + 0);
            *(float4*)&v[4]  = *(const float4*)(xs + 4);
            *(float4*)&v[8]  = *(const float4*)(xs + 8);
            *(float4*)&v[12] = *(const float4*)(xs + 12);
            uint4 h0, l0, h1, l1;
            split8(v,     &h0, &l0);
            split8(v + 8, &h1, &l1);
            *(uint4*)(bufp + 16384 + bo0) = h0;
            *(uint4*)(bufp + 16384 + bo1) = h1;
            *(uint4*)(bufp + 24576 + bo0) = l0;
            *(uint4*)(bufp + 24576 + bo1) = l1;
        }
        __syncthreads();   // Bh/Bl visible to all warps

        if (kc + 1 < NC) STAGE(cur ^ 1, kc + 1);   // overlaps with MMA below

        uint32_t base = smb + cur * BUFSZ;
#pragma unroll
        for (int ks = 0; ks < 2; ks++) {
            uint32_t bhf[2][4], blf[2][4];
            int brow = ks * 16 + (lane & 15);
            int nbb  = (n_off >> 3) + (lane >> 4);
#pragma unroll
            for (int nip = 0; nip < 2; nip++) {
                uint32_t boff = brow * 256 + (((nbb + nip * 2) ^ (brow & 7)) << 4);
                ldm_x4t(bhf[nip], base + 16384 + boff);
                ldm_x4t(blf[nip], base + 24576 + boff);
            }
#pragma unroll
            for (int mi = 0; mi < 4; mi++) {
                int arow = m_off + mi * 16 + (lane & 15);
                int cb   = ks * 2 + (lane >> 4);
                uint32_t aoff = arow * 64 + ((cb ^ ((arow >> 1) & 3)) << 4);
                uint32_t ah[4], al[4];
                ldm_x4(ah, base + aoff);
                ldm_x4(al, base + 8192 + aoff);
#pragma unroll
                for (int ni = 0; ni < 4; ni++) {
                    const uint32_t* bh = &bhf[ni >> 1][(ni & 1) * 2];
                    const uint32_t* bl = &blf[ni >> 1][(ni & 1) * 2];
                    mma16(acc[mi][ni], ah, bh);
                    mma16(acc[mi][ni], ah, bl);
                    mma16(acc[mi][ni], al, bh);
                }
            }
        }
        cur ^= 1;
    }

    const float* gg  = P.gg[lvl];
    const float* bbp = P.bb[lvl];
    const float* mm  = P.mm[lvl];
    const float* vv  = P.vv[lvl];
    float*       pf  = P.pf[lvl];
#pragma unroll
    for (int mi = 0; mi < 4; mi++) {
        int r0 = d0 + m_off + mi * 16 + g;
        int r1 = r0 + 8;
        float sc0 = gg[r0] * (1.0f / sqrtf(vv[r0] + 1e-5f));
        float bi0 = bbp[r0] - mm[r0] * sc0;
        float sc1 = gg[r1] * (1.0f / sqrtf(vv[r1] + 1e-5f));
        float bi1 = bbp[r1] - mm[r1] * sc1;
        float* op0 = pf + ((size_t)n * C + r0) * HW;
        float* op1 = pf + ((size_t)n * C + r1) * HW;
#pragma unroll
        for (int ni = 0; ni < 4; ni++) {
            int p = p0 + n_off + ni * 8 + 2 * tg;
            if (p < HW) {
                *(float2*)(op0 + p) = make_float2(silu(acc[mi][ni][0] * sc0 + bi0),
                                                  silu(acc[mi][ni][1] * sc0 + bi0));
                *(float2*)(op1 + p) = make_float2(silu(acc[mi][ni][2] * sc1 + bi1),
                                                  silu(acc[mi][ni][3] * sc1 + bi1));
            }
        }
    }
}

// ---------------- corr (R8 known-good) --------------------------------------------
template<int C, int H, int W, int STEP, int NG, int NT, int WINL>
__global__ void __launch_bounds__(NT) corr2_kernel(
    const float* __restrict__ pf, const float* __restrict__ mlpw,
    float* __restrict__ out, int out_off)
{
    constexpr int PAD = RAD * STEP;
    constexpr int W2  = W + 2 * PAD;
    constexpr int H2  = H + 2 * PAD;
    constexpr int HW  = H * W;
    constexpr int NW  = NT / 32;

    extern __shared__ float sm[];
    float* f1p  = sm;
    float* wred = sm + H2 * W2;

    const int c    = blockIdx.x;
    const int b    = blockIdx.y;
    const int n1   = b * TPP + (TPP - 1);
    const int n2a  = g_idx[b * TFF + 0];
    const int n2b  = g_idx[b * TFF + 1];
    const int tid  = threadIdx.x;
    const int wid  = tid >> 5;
    const int lane = tid & 31;

    const float* f1g = pf + ((size_t)n1  * C + c) * HW;
    const float* f2a = pf + ((size_t)n2a * C + c) * HW;
    const float* f2b = pf + ((size_t)n2b * C + c) * HW;

    for (int q = tid; q < H2 * W2; q += NT) {
        int hh = q / W2 - PAD;
        int ww = q % W2 - PAD;
        float v = 0.f;
        if ((unsigned)hh < (unsigned)H && (unsigned)ww < (unsigned)W)
            v = f1g[hh * W + ww];
        f1p[q] = v;
    }

    float fra[NG][4], frb[NG][4];
    int   basek[NG];
#pragma unroll
    for (int gi = 0; gi < NG; gi++) {
        int p = (tid + NT * gi) * 4;
        if (p < HW) {
            float4 va = *(const float4*)(f2a + p);
            float4 vb = *(const float4*)(f2b + p);
            fra[gi][0] = va.x; fra[gi][1] = va.y; fra[gi][2] = va.z; fra[gi][3] = va.w;
            frb[gi][0] = vb.x; frb[gi][1] = vb.y; frb[gi][2] = vb.z; frb[gi][3] = vb.w;
            basek[gi] = (p / W + PAD) * W2 + (p % W) + PAD;
        } else {
#pragma unroll
            for (int v = 0; v < 4; v++) { fra[gi][v] = 0.f; frb[gi][v] = 0.f; }
            basek[gi] = PAD * W2 + PAD;
        }
    }
    __syncthreads();

    if (WINL == 0) {
        for (int oy = 0; oy < 9; oy++) {
            int ro[NG];
            int dyo = (oy - RAD) * STEP * W2;
#pragma unroll
            for (int gi = 0; gi < NG; gi++) ro[gi] = basek[gi] + dyo;
#pragma unroll
            for (int ox = 0; ox < 9; ox++) {
                const int dxo = (ox - RAD) * STEP;
                float a0 = 0.f, a1 = 0.f, b0 = 0.f, b1 = 0.f;
#pragma unroll
                for (int gi = 0; gi < NG; gi++) {
                    float4 fv = *(const float4*)&f1p[ro[gi] + dxo];
                    a0 = fmaf(fv.x, fra[gi][0], a0);
                    a1 = fmaf(fv.y, fra[gi][1], a1);
                    a0 = fmaf(fv.z, fra[gi][2], a0);
                    a1 = fmaf(fv.w, fra[gi][3], a1);
                    b0 = fmaf(fv.x, frb[gi][0], b0);
                    b1 = fmaf(fv.y, frb[gi][1], b1);
                    b0 = fmaf(fv.z, frb[gi][2], b0);
                    b1 = fmaf(fv.w, frb[gi][3], b1);
                }
                float va = a0 + a1, vb = b0 + b1;
#pragma unroll
                for (int o = 16; o; o >>= 1) {
                    va += __shfl_xor_sync(0xffffffffu, va, o);
                    vb += __shfl_xor_sync(0xffffffffu, vb, o);
                }
                if (lane == 0) {
                    wred[(0 * NW + wid) * NS + oy * 9 + ox] = va;
                    wred[(1 * NW + wid) * NS + oy * 9 + ox] = vb;
                }
            }
        }
    } else {
        for (int oy = 0; oy < 9; oy++) {
            int dyo = (oy - RAD) * STEP * W2;
            float aA[9], aB[9];
#pragma unroll
            for (int ox = 0; ox < 9; ox++) { aA[ox] = 0.f; aB[ox] = 0.f; }
#pragma unroll
            for (int gi = 0; gi < NG; gi++) {
                const float* wp = &f1p[basek[gi] + dyo - 4 * STEP];
                float win[WINL > 0 ? WINL : 1];
#pragma unroll
                for (int t = 0; t < WINL / 4; t++) {
                    float4 v = *(const float4*)(wp + 4 * t);
                    win[4 * t] = v.x; win[4 * t + 1] = v.y;
                    win[4 * t + 2] = v.z; win[4 * t + 3] = v.w;
                }
#pragma unroll
                for (int ox = 0; ox < 9; ox++) {
#pragma unroll
                    for (int j = 0; j < 4; j++) {
                        aA[ox] = fmaf(win[STEP * ox + j], fra[gi][j], aA[ox]);
                        aB[ox] = fmaf(win[STEP * ox + j], frb[gi][j], aB[ox]);
                    }
                }
            }
#pragma unroll
            for (int ox = 0; ox < 9; ox++) {
                float va = aA[ox], vb = aB[ox];
#pragma unroll
                for (int o = 16; o; o >>= 1) {
                    va += __shfl_xor_sync(0xffffffffu, va, o);
                    vb += __shfl_xor_sync(0xffffffffu, vb, o);
                }
                if (lane == 0) {
                    wred[(0 * NW + wid) * NS + oy * 9 + ox] = va;
                    wred[(1 * NW + wid) * NS + oy * 9 + ox] = vb;
                }
            }
        }
    }
    __syncthreads();

    if (tid < 64) {
        int q = tid >> 5, l = tid & 31;
        const float* wr = wred + q * NW * NS;
        float v0, v1 = -1e30f, v2 = -1e30f;
        {
            float s0 = 0.f, s1 = 0.f, s2 = 0.f;
#pragma unroll
            for (int w = 0; w < NW; w++) {
                s0 += wr[w * NS + l];
                if (l + 32 < NS) s1 += wr[w * NS + l + 32];
                if (l + 64 < NS) s2 += wr[w * NS + l + 64];
            }
            v0 = s0;
            if (l + 32 < NS) v1 = s1;
            if (l + 64 < NS) v2 = s2;
        }
        float mx = fmaxf(v0, fmaxf(v1, v2));
#pragma unroll
        for (int o = 16; o; o >>= 1)
            mx = fmaxf(mx, __shfl_xor_sync(0xffffffffu, mx, o));
        float e0 = expf(v0 - mx);
        float e1 = (l + 32 < NS) ? expf(v1 - mx) : 0.f;
        float e2 = (l + 64 < NS) ? expf(v2 - mx) : 0.f;
        float w0 = mlpw[l];
        float w1 = (l + 32 < NS) ? mlpw[l + 32] : 0.f;
        float w2 = (l + 64 < NS) ? mlpw[l + 64] : 0.f;
        float ssum = e0 + e1 + e2;
        float dot  = e0 * w0 + e1 * w1 + e2 * w2;
#pragma unroll
        for (int o = 16; o; o >>= 1) {
            ssum += __shfl_xor_sync(0xffffffffu, ssum, o);
            dot  += __shfl_xor_sync(0xffffffffu, dot,  o);
        }
        if (l == 0)
            out[out_off + (b * TFF + q) * C + c] = dot / ssum;
    }
}

// ---------------- launch ----------------------------------------------------------
extern "C" void kernel_launch(void* const* d_in, const int* in_sizes, int n_in,
                              void* d_out, int out_size)
{
    int map_sig [21] = {0,1,2, 3,4,5,6,7, 8,9,10,11,12, 13,14,15,16,17, 18,19,20};
    int map_dict[21] = {0,6,12, 1,2,3,4,5, 7,8,9,10,11, 13,14,15,16,17, 18,19,20};
    const int* map = (in_sizes[1] == 16384) ? map_dict : map_sig;

    const float* mlpw = (const float*)d_in[map[18]];
    const int*   pci  = (const int*)d_in[map[19]];
    const int*   fci  = (const int*)d_in[map[20]];
    float* out = (float*)d_out;

    void* pv;
    cudaGetSymbolAddress(&pv, g_pf0);  float* pf0 = (float*)pv;
    cudaGetSymbolAddress(&pv, g_pf1);  float* pf1 = (float*)pv;
    cudaGetSymbolAddress(&pv, g_pf2);  float* pf2 = (float*)pv;
    __nv_bfloat16 *w0a, *w0b, *w1a, *w1b, *w2a, *w2b;
    cudaGetSymbolAddress(&pv, g_w0a); w0a = (__nv_bfloat16*)pv;
    cudaGetSymbolAddress(&pv, g_w0b); w0b = (__nv_bfloat16*)pv;
    cudaGetSymbolAddress(&pv, g_w1a); w1a = (__nv_bfloat16*)pv;
    cudaGetSymbolAddress(&pv, g_w1b); w1b = (__nv_bfloat16*)pv;
    cudaGetSymbolAddress(&pv, g_w2a); w2a = (__nv_bfloat16*)pv;
    cudaGetSymbolAddress(&pv, g_w2b); w2b = (__nv_bfloat16*)pv;

    prep_kernel<<<1, 1>>>(pci, fci);

    SplitW SW;
    SW.w[0] = (const float*)d_in[map[3]];
    SW.w[1] = (const float*)d_in[map[8]];
    SW.w[2] = (const float*)d_in[map[13]];
    SW.wa[0] = w0a; SW.wa[1] = w1a; SW.wa[2] = w2a;
    SW.wb[0] = w0b; SW.wb[1] = w1b; SW.wb[2] = w2b;
    wsplit_all<<<dim3(128, 3), 256>>>(SW);

    ConvTC P;
    P.wa[0] = w0a; P.wa[1] = w1a; P.wa[2] = w2a;
    P.wb[0] = w0b; P.wb[1] = w1b; P.wb[2] = w2b;
    P.x[0] = (const float*)d_in[map[0]];
    P.x[1] = (const float*)d_in[map[1]];
    P.x[2] = (const float*)d_in[map[2]];
    P.gg[0] = (const float*)d_in[map[4]];  P.gg[1] = (const float*)d_in[map[9]];   P.gg[2] = (const float*)d_in[map[14]];
    P.bb[0] = (const float*)d_in[map[5]];  P.bb[1] = (const float*)d_in[map[10]];  P.bb[2] = (const float*)d_in[map[15]];
    P.mm[0] = (const float*)d_in[map[6]];  P.mm[1] = (const float*)d_in[map[11]];  P.mm[2] = (const float*)d_in[map[16]];
    P.vv[0] = (const float*)d_in[map[7]];  P.vv[1] = (const float*)d_in[map[12]];  P.vv[2] = (const float*)d_in[map[17]];
    P.pf[0] = pf0; P.pf[1] = pf1; P.pf[2] = pf2;

    cudaFuncSetAttribute(conv_bf16_kernel,
                         cudaFuncAttributeMaxDynamicSharedMemorySize, 2 * BUFSZ);
    conv_bf16_kernel<<<dim3(92, 1, NFR), 256, 2 * BUFSZ>>>(P);

    size_t sm0 = (size_t)(112 * 112 + 2 * 8 * NS) * sizeof(float);
    size_t sm1 = (size_t)( 56 *  56 + 2 * 8 * NS) * sizeof(float);
    size_t sm2 = (size_t)( 28 *  28 + 2 * 4 * NS) * sizeof(float);
    cudaFuncSetAttribute((const void*)corr2_kernel<128, 80, 80, 4, 7, 256, 0>,
                         cudaFuncAttributeMaxDynamicSharedMemorySize, 65536);

    corr2_kernel<128, 80, 80, 4, 7, 256,  0><<<dim3(128, BB), 256, sm0>>>(pf0, mlpw, out, 0);
    corr2_kernel<256, 40, 40, 2, 2, 256, 20><<<dim3(256, BB), 256, sm1>>>(pf1, mlpw, out, 1024);
    corr2_kernel<512, 20, 20, 1, 1, 128, 12><<<dim3(512, BB), 128, sm2>>>(pf2, mlpw, out, 3072);
}